// round 11
// baseline (speedup 1.0000x reference)
#include <cuda_runtime.h>
#include <cuda_fp16.h>
#include <cstdint>

#define DIMC   512
#define HEADS  8
#define HD     64
#define NTOK   64
#define BATCH  2048
#define MROWS  (BATCH * NTOK)     // 131072
#define SCALE_Q 0.125f

// ---------------- device scratch ----------------
__device__ float g_y[(size_t)3 * MROWS * DIMC];                    // Qh|Kh|Vh
__device__ float g_x[(size_t)MROWS * DIMC];                        // attn out
__device__ __align__(128) __half g_wblob[(size_t)4 * 512 * 512];   // W hi (fp16)

// ---------------------------------------------------------------------------
// Kernel 0: weights -> fp16 blobs ([n][k] row-major).
// ---------------------------------------------------------------------------
__global__ void conv_w(const float* __restrict__ Wq, const float* __restrict__ Wk,
                       const float* __restrict__ Wv, const float* __restrict__ Wp) {
    int idx = blockIdx.x * 256 + threadIdx.x;
    int g   = idx >> 18;
    int rem = idx & 262143;
    const float* W = (g == 0) ? Wq : (g == 1) ? Wk : (g == 2) ? Wv : Wp;
    g_wblob[(size_t)g * 262144 + rem] = __float2half_rn(W[rem]);
}

// ---------------------------------------------------------------------------
// common MMA helpers
// ---------------------------------------------------------------------------
__device__ __forceinline__ void mma16816(float* d, const uint32_t* a, const uint32_t* b) {
    asm volatile(
        "mma.sync.aligned.m16n8k16.row.col.f32.f16.f16.f32 "
        "{%0,%1,%2,%3}, {%4,%5,%6,%7}, {%8,%9}, {%0,%1,%2,%3};"
        : "+f"(d[0]), "+f"(d[1]), "+f"(d[2]), "+f"(d[3])
        : "r"(a[0]), "r"(a[1]), "r"(a[2]), "r"(a[3]), "r"(b[0]), "r"(b[1]));
}
__device__ __forceinline__ void ldsm_x4(uint32_t* r, uint32_t addr) {
    asm volatile("ldmatrix.sync.aligned.m8n8.x4.shared.b16 {%0,%1,%2,%3}, [%4];"
        : "=r"(r[0]), "=r"(r[1]), "=r"(r[2]), "=r"(r[3]) : "r"(addr));
}
__device__ __forceinline__ void cp16(uint32_t dst, const void* src) {
    asm volatile("cp.async.cg.shared.global [%0], [%1], 16;" :: "r"(dst), "l"(src));
}
__device__ __forceinline__ uint32_t pack_h(__half a, __half b) {
    return (uint32_t)__half_as_ushort(a) | ((uint32_t)__half_as_ushort(b) << 16);
}

// ---------------------------------------------------------------------------
// GEMM: C[131072,512] = A @ W^T + bias. fp16 hi/lo 2-product mma.sync.
// CTA 128m x 256n, 512 threads = 16 warps (4m x 4n), warp tile 32x64.
// K chunks of 64 (8 chunks), 3-stage cp.async pipeline, 1 barrier per chunk.
// ---------------------------------------------------------------------------
#define KC      64
#define SAK     72
#define OFF_AH  0
#define OFF_AL  (128 * SAK)
#define OFF_BH  (2 * 128 * SAK)
#define STAGE_E (2 * 128 * SAK + 256 * SAK)       // 36864 fp16 elems = 73728 B
#define SMEM_G  (3 * STAGE_E * 2)                  // 221184 bytes

__global__ __launch_bounds__(512, 1)
void gemm_mma(const float* __restrict__ qin, const float* __restrict__ kin,
              const float* __restrict__ vin, const float* __restrict__ bias,
              float* __restrict__ Cext, int g) {
    extern __shared__ __half sm[];
    const uint32_t sb = (uint32_t)__cvta_generic_to_shared(sm);

    const float* A = (g == 0) ? qin : (g == 1) ? kin : (g == 2) ? vin : (const float*)g_x;
    float* C = (g < 3) ? (g_y + (size_t)g * MROWS * DIMC) : Cext;
    const __half* Wh = g_wblob + (size_t)g * 262144;

    const int tid  = threadIdx.x;
    const int lane = tid & 31;
    const int wid  = tid >> 5;
    const int wm   = (wid >> 2) * 32;
    const int wn   = (wid & 3) * 64;
    const int n0   = blockIdx.x * 256;
    const int m0   = blockIdx.y * 128;

    // A staging: 4 threads per row, 16 floats each
    const int arow  = tid >> 2;
    const int acolf = (tid & 3) * 16;
    // B staging: 2 threads per row (256 rows), 32 halves each
    const int brow  = tid >> 1;
    const int bcolf = (tid & 1) * 32;

    // ldmatrix lane offsets
    const int a_lrow = (lane & 15);
    const int a_lcol = (lane >> 4) * 8;
    const int b_lrow = ((lane >> 4) << 3) + (lane & 7);
    const int b_lcol = ((lane >> 3) & 1) * 8;

    float acc[2][8][4];
    #pragma unroll
    for (int i = 0; i < 2; i++)
        #pragma unroll
        for (int j = 0; j < 8; j++)
            #pragma unroll
            for (int r = 0; r < 4; r++) acc[i][j][r] = 0.f;

    float4 rA[4];

    auto stageB = [&](int c, int st) {
        uint32_t dst = sb + (uint32_t)(st * STAGE_E + OFF_BH + brow * SAK + bcolf) * 2;
        const __half* src = Wh + (size_t)(n0 + brow) * DIMC + c * KC + bcolf;
        #pragma unroll
        for (int u = 0; u < 4; u++) cp16(dst + u * 16, src + u * 8);
    };
    auto ldgA = [&](int c) {
        const float* src = A + (size_t)(m0 + arow) * DIMC + c * KC + acolf;
        #pragma unroll
        for (int u = 0; u < 4; u++) rA[u] = __ldg((const float4*)(src + u * 4));
    };
    auto stsA = [&](int st) {
        __half* sAh = sm + st * STAGE_E + OFF_AH + arow * SAK + acolf;
        __half* sAl = sm + st * STAGE_E + OFF_AL + arow * SAK + acolf;
        #pragma unroll
        for (int u = 0; u < 4; u++) {
            float4 f = rA[u];
            __half h0 = __float2half_rn(f.x), h1 = __float2half_rn(f.y),
                   h2 = __float2half_rn(f.z), h3 = __float2half_rn(f.w);
            __half l0 = __float2half_rn(f.x - __half2float(h0));
            __half l1 = __float2half_rn(f.y - __half2float(h1));
            __half l2 = __float2half_rn(f.z - __half2float(h2));
            __half l3 = __float2half_rn(f.w - __half2float(h3));
            *(uint2*)(sAh + u * 4) = make_uint2(pack_h(h0, h1), pack_h(h2, h3));
            *(uint2*)(sAl + u * 4) = make_uint2(pack_h(l0, l1), pack_h(l2, l3));
        }
    };
    auto compute = [&](int st) {
        const uint32_t abase = sb + (uint32_t)(st * STAGE_E) * 2;
        #pragma unroll
        for (int ks = 0; ks < 4; ks++) {
            const int kc0 = ks * 16;
            uint32_t bf[8][2];
            uint32_t ah[2][4], al[2][4];
            #pragma unroll
            for (int i = 0; i < 2; i++) {
                uint32_t aaddr = abase + (uint32_t)(OFF_AH +
                    (wm + i * 16 + a_lrow) * SAK + kc0 + a_lcol) * 2;
                ldsm_x4(ah[i], aaddr);
                ldsm_x4(al[i], aaddr + (uint32_t)(OFF_AL - OFF_AH) * 2);
            }
            #pragma unroll
            for (int gg = 0; gg < 4; gg++) {
                uint32_t r[4];
                uint32_t addr = abase + (uint32_t)(OFF_BH +
                    (wn + gg * 16 + b_lrow) * SAK + kc0 + b_lcol) * 2;
                ldsm_x4(r, addr);
                bf[2 * gg][0] = r[0]; bf[2 * gg][1] = r[1];
                bf[2 * gg + 1][0] = r[2]; bf[2 * gg + 1][1] = r[3];
            }
            #pragma unroll
            for (int i = 0; i < 2; i++)
                #pragma unroll
                for (int j = 0; j < 8; j++)
                    mma16816(acc[i][j], ah[i], bf[j]);
            #pragma unroll
            for (int i = 0; i < 2; i++)
                #pragma unroll
                for (int j = 0; j < 8; j++)
                    mma16816(acc[i][j], al[i], bf[j]);
        }
    };

    // ---- prologue ----
    stageB(0, 0);
    asm volatile("cp.async.commit_group;" ::: "memory");
    ldgA(0);
    stsA(0);

    // ---- main pipeline: 8 chunks, 3 stages, 1 barrier per chunk ----
    for (int c = 0; c < 8; c++) {
        const int st  = c % 3;
        const int stn = (c + 1) % 3;
        if (c < 7) {
            ldgA(c + 1);
            stageB(c + 1, stn);
            asm volatile("cp.async.commit_group;" ::: "memory");
            asm volatile("cp.async.wait_group 1;" ::: "memory");
        } else {
            asm volatile("cp.async.wait_group 0;" ::: "memory");
        }
        __syncthreads();
        compute(st);
        if (c < 7) stsA(stn);
    }

    // ---- epilogue ----
    #pragma unroll
    for (int j = 0; j < 8; j++) {
        int col = n0 + wn + j * 8 + (lane & 3) * 2;
        float b0 = __ldg(bias + col), b1 = __ldg(bias + col + 1);
        #pragma unroll
        for (int i = 0; i < 2; i++) {
            int row = m0 + wm + i * 16 + (lane >> 2);
            *(float2*)(C + (size_t)row * DIMC + col) =
                make_float2(acc[i][j][0] + b0, acc[i][j][1] + b1);
            *(float2*)(C + (size_t)(row + 8) * DIMC + col) =
                make_float2(acc[i][j][2] + b0, acc[i][j][3] + b1);
        }
    }
}

// ---------------------------------------------------------------------------
// Attention per (b,h) — tensor-core fp16 hi/lo (unchanged from R9).
// ---------------------------------------------------------------------------
#define SK2   72
#define TQH   0
#define TQL   4608
#define TKH   9216
#define TVT   13824
#define OFF_S 36864
#define OFF_M 54272
#define SMEM_A 54528

__global__ __launch_bounds__(128, 4)
void attn(const int* __restrict__ mask) {
    extern __shared__ __half sha[];
    __half* sQh = sha + TQH;
    __half* sQl = sha + TQL;
    __half* sKh = sha + TKH;
    __half* sVt = sha + TVT;
    float*  sS  = (float*)((char*)sha + OFF_S);
    int*  smask = (int*)((char*)sha + OFF_M);
    const uint32_t sb = (uint32_t)__cvta_generic_to_shared(sha);

    const int blk  = blockIdx.x;
    const int h    = blk & (HEADS - 1);
    const int b    = blk >> 3;
    const int tid  = threadIdx.x;
    const int lane = tid & 31;
    const int wid  = tid >> 5;
    const int wm   = wid * 16;

    const float* Yq = g_y;
    const float* Yk = g_y + (size_t)MROWS * DIMC;
    const float* Yv = g_y + (size_t)2 * MROWS * DIMC;

    if (tid < NTOK) smask[tid] = mask[b * NTOK + tid];

    {
        const int row = tid >> 1;
        const int d0  = (tid & 1) * 32;
        const size_t off = (size_t)(b * 64 + row) * 512 + h * 64 + d0;
        #pragma unroll
        for (int u = 0; u < 8; u++) {
            float4 fq = __ldg((const float4*)(Yq + off + u * 4));
            float4 fk = __ldg((const float4*)(Yk + off + u * 4));
            float4 fv = __ldg((const float4*)(Yv + off + u * 4));
            float qs[4] = {fq.x * SCALE_Q, fq.y * SCALE_Q, fq.z * SCALE_Q, fq.w * SCALE_Q};
            __half qh[4], ql[4];
            #pragma unroll
            for (int e = 0; e < 4; e++) {
                qh[e] = __float2half_rn(qs[e]);
                ql[e] = __float2half_rn(qs[e] - __half2float(qh[e]));
            }
            int d = d0 + u * 4;
            *(uint2*)(sQh + row * SK2 + d) = make_uint2(pack_h(qh[0], qh[1]), pack_h(qh[2], qh[3]));
            *(uint2*)(sQl + row * SK2 + d) = make_uint2(pack_h(ql[0], ql[1]), pack_h(ql[2], ql[3]));
            *(uint2*)(sKh + row * SK2 + d) = make_uint2(
                pack_h(__float2half_rn(fk.x), __float2half_rn(fk.y)),
                pack_h(__float2half_rn(fk.z), __float2half_rn(fk.w)));
            sVt[(d + 0) * SK2 + row] = __float2half_rn(fv.x);
            sVt[(d + 1) * SK2 + row] = __float2half_rn(fv.y);
            sVt[(d + 2) * SK2 + row] = __float2half_rn(fv.z);
            sVt[(d + 3) * SK2 + row] = __float2half_rn(fv.w);
        }
    }
    __syncthreads();

    const int a_lrow = (lane & 15);
    const int a_lcol = (lane >> 4) * 8;
    const int b_lrow = ((lane >> 4) << 3) + (lane & 7);
    const int b_lcol = ((lane >> 3) & 1) * 8;

    {
        float acc[8][4];
        #pragma unroll
        for (int j = 0; j < 8; j++)
            #pragma unroll
            for (int r = 0; r < 4; r++) acc[j][r] = 0.f;
        #pragma unroll
        for (int ks = 0; ks < 4; ks++) {
            const int kc0 = ks * 16;
            uint32_t qh[4], ql[4], bf[8][2];
            uint32_t qaddr = sb + (uint32_t)(TQH + (wm + a_lrow) * SK2 + kc0 + a_lcol) * 2;
            ldsm_x4(qh, qaddr);
            ldsm_x4(ql, qaddr + (uint32_t)(TQL - TQH) * 2);
            #pragma unroll
            for (int gg = 0; gg < 4; gg++) {
                uint32_t r[4];
                ldsm_x4(r, sb + (uint32_t)(TKH + (gg * 16 + b_lrow) * SK2 + kc0 + b_lcol) * 2);
                bf[2 * gg][0] = r[0]; bf[2 * gg][1] = r[1];
                bf[2 * gg + 1][0] = r[2]; bf[2 * gg + 1][1] = r[3];
            }
            #pragma unroll
            for (int j = 0; j < 8; j++) mma16816(acc[j], qh, bf[j]);
            #pragma unroll
            for (int j = 0; j < 8; j++) mma16816(acc[j], ql, bf[j]);
        }
        #pragma unroll
        for (int j = 0; j < 8; j++) {
            int col = j * 8 + (lane & 3) * 2;
            int r0  = wm + (lane >> 2);
            sS[r0 * 68 + col]       = acc[j][0];
            sS[r0 * 68 + col + 1]   = acc[j][1];
            sS[(r0 + 8) * 68 + col]     = acc[j][2];
            sS[(r0 + 8) * 68 + col + 1] = acc[j][3];
        }
    }
    __syncthreads();

    {
        const int row = tid >> 1;
        const int p   = tid & 1;
        float v[32];
        float m = -1e30f;
        #pragma unroll
        for (int s = 0; s < 32; s++) {
            int j = p * 32 + s;
            float sv = sS[row * 68 + j];
            v[s] = (smask[j] != 0) ? sv : -10000.0f;
            m = fmaxf(m, v[s]);
        }
        m = fmaxf(m, __shfl_xor_sync(0xffffffffu, m, 1));
        float sum = 0.f;
        #pragma unroll
        for (int s = 0; s < 32; s++) { v[s] = __expf(v[s] - m); sum += v[s]; }
        sum += __shfl_xor_sync(0xffffffffu, sum, 1);
        float inv = 1.0f / sum;
        #pragma unroll
        for (int s = 0; s < 32; s++) {
            int j = p * 32 + s;
            float pv = v[s] * inv;
            __half ph = __float2half_rn(pv);
            sQh[row * SK2 + j] = ph;
            sQl[row * SK2 + j] = __float2half_rn(pv - __half2float(ph));
        }
    }
    __syncthreads();

    {
        float acc[8][4];
        #pragma unroll
        for (int j = 0; j < 8; j++)
            #pragma unroll
            for (int r = 0; r < 4; r++) acc[j][r] = 0.f;
        #pragma unroll
        for (int ks = 0; ks < 4; ks++) {
            const int kc0 = ks * 16;
            uint32_t ph[4], pl[4], bf[8][2];
            uint32_t paddr = sb + (uint32_t)(TQH + (wm + a_lrow) * SK2 + kc0 + a_lcol) * 2;
            ldsm_x4(ph, paddr);
            ldsm_x4(pl, paddr + (uint32_t)(TQL - TQH) * 2);
            #pragma unroll
            for (int gg = 0; gg < 4; gg++) {
                uint32_t r[4];
                ldsm_x4(r, sb + (uint32_t)(TVT + (gg * 16 + b_lrow) * SK2 + kc0 + b_lcol) * 2);
                bf[2 * gg][0] = r[0]; bf[2 * gg][1] = r[1];
                bf[2 * gg + 1][0] = r[2]; bf[2 * gg + 1][1] = r[3];
            }
            #pragma unroll
            for (int j = 0; j < 8; j++) mma16816(acc[j], ph, bf[j]);
            #pragma unroll
            for (int j = 0; j < 8; j++) mma16816(acc[j], pl, bf[j]);
        }
        #pragma unroll
        for (int j = 0; j < 8; j++) {
            int col = h * HD + j * 8 + (lane & 3) * 2;
            int r0  = wm + (lane >> 2);
            *(float2*)(g_x + (size_t)(b * 64 + r0) * DIMC + col) =
                make_float2(acc[j][0], acc[j][1]);
            *(float2*)(g_x + (size_t)(b * 64 + r0 + 8) * DIMC + col) =
                make_float2(acc[j][2], acc[j][3]);
        }
    }
}

// ---------------------------------------------------------------------------
extern "C" void kernel_launch(void* const* d_in, const int* in_sizes, int n_in,
                              void* d_out, int out_size) {
    const float* q    = (const float*)d_in[0];
    const float* k    = (const float*)d_in[1];
    const float* v    = (const float*)d_in[2];
    const int*   mask = (const int*)  d_in[3];
    const float* Wq   = (const float*)d_in[4];
    const float* bq   = (const float*)d_in[5];
    const float* Wk   = (const float*)d_in[6];
    const float* bk   = (const float*)d_in[7];
    const float* Wv   = (const float*)d_in[8];
    const float* bv   = (const float*)d_in[9];
    const float* Wp   = (const float*)d_in[10];
    const float* bp   = (const float*)d_in[11];
    float* out = (float*)d_out;

    cudaFuncSetAttribute(gemm_mma, cudaFuncAttributeMaxDynamicSharedMemorySize, SMEM_G);
    cudaFuncSetAttribute(attn, cudaFuncAttributeMaxDynamicSharedMemorySize, SMEM_A);

    conv_w<<<4096, 256>>>(Wq, Wk, Wv, Wp);

    dim3 gg(DIMC / 256, MROWS / 128);
    gemm_mma<<<gg, 512, SMEM_G>>>(q, k, v, bq, nullptr, 0);
    gemm_mma<<<gg, 512, SMEM_G>>>(q, k, v, bk, nullptr, 1);
    gemm_mma<<<gg, 512, SMEM_G>>>(q, k, v, bv, nullptr, 2);

    attn<<<BATCH * HEADS, 128, SMEM_A>>>(mask);

    gemm_mma<<<gg, 512, SMEM_G>>>(q, k, v, bp, out, 3);
}

// round 12
// speedup vs baseline: 1.0509x; 1.0509x over previous
#include <cuda_runtime.h>
#include <cuda_fp16.h>
#include <cstdint>

#define DIMC   512
#define HEADS  8
#define HD     64
#define NTOK   64
#define BATCH  2048
#define MROWS  (BATCH * NTOK)     // 131072
#define SCALE_Q 0.125f

// ---------------- device scratch ----------------
__device__ __half g_qh[(size_t)MROWS * DIMC];   // Q hi (scale folded)
__device__ __half g_ql[(size_t)MROWS * DIMC];   // Q lo
__device__ __half g_kh[(size_t)MROWS * DIMC];   // K hi
__device__ __half g_vt[(size_t)MROWS * DIMC];   // V hi, transposed [b][h][d][token]
__device__ float  g_x [(size_t)MROWS * DIMC];   // attn out (fp32)
__device__ __align__(128) __half g_wblob[(size_t)4 * 512 * 512];

// ---------------------------------------------------------------------------
// Kernel 0: weights -> fp16 blobs. Wq pre-scaled by SCALE_Q (exact pow2).
// ---------------------------------------------------------------------------
__global__ void conv_w(const float* __restrict__ Wq, const float* __restrict__ Wk,
                       const float* __restrict__ Wv, const float* __restrict__ Wp) {
    int idx = blockIdx.x * 256 + threadIdx.x;
    int g   = idx >> 18;
    int rem = idx & 262143;
    const float* W = (g == 0) ? Wq : (g == 1) ? Wk : (g == 2) ? Wv : Wp;
    float w = W[rem] * ((g == 0) ? SCALE_Q : 1.0f);
    g_wblob[(size_t)g * 262144 + rem] = __float2half_rn(w);
}

// ---------------------------------------------------------------------------
// common MMA helpers
// ---------------------------------------------------------------------------
__device__ __forceinline__ void mma16816(float* d, const uint32_t* a, const uint32_t* b) {
    asm volatile(
        "mma.sync.aligned.m16n8k16.row.col.f32.f16.f16.f32 "
        "{%0,%1,%2,%3}, {%4,%5,%6,%7}, {%8,%9}, {%0,%1,%2,%3};"
        : "+f"(d[0]), "+f"(d[1]), "+f"(d[2]), "+f"(d[3])
        : "r"(a[0]), "r"(a[1]), "r"(a[2]), "r"(a[3]), "r"(b[0]), "r"(b[1]));
}
__device__ __forceinline__ void ldsm_x4(uint32_t* r, uint32_t addr) {
    asm volatile("ldmatrix.sync.aligned.m8n8.x4.shared.b16 {%0,%1,%2,%3}, [%4];"
        : "=r"(r[0]), "=r"(r[1]), "=r"(r[2]), "=r"(r[3]) : "r"(addr));
}
__device__ __forceinline__ void cp16(uint32_t dst, const void* src) {
    asm volatile("cp.async.cg.shared.global [%0], [%1], 16;" :: "r"(dst), "l"(src));
}
__device__ __forceinline__ uint32_t pack_h(__half a, __half b) {
    return (uint32_t)__half_as_ushort(a) | ((uint32_t)__half_as_ushort(b) << 16);
}

// ---------------------------------------------------------------------------
// GEMM mainloop (R9 config: KC=32, SAK=40, 3-stage — best measured, 392us).
// Epilogue varies by g: 0=Q->hi/lo fp16, 1=K->fp16, 2=V->fp16 transposed,
// 3=proj->fp32 out.
// ---------------------------------------------------------------------------
#define KC      32
#define SAK     40
#define OFF_AH  0
#define OFF_AL  (128 * SAK)
#define OFF_BH  (2 * 128 * SAK)
#define STAGE_E (2 * 128 * SAK + 256 * SAK)
#define SMEM_G  (3 * STAGE_E * 2)

__global__ __launch_bounds__(512, 1)
void gemm_mma(const float* __restrict__ qin, const float* __restrict__ kin,
              const float* __restrict__ vin, const float* __restrict__ bias,
              float* __restrict__ Cext, int g) {
    extern __shared__ __half sm[];
    const uint32_t sb = (uint32_t)__cvta_generic_to_shared(sm);

    const float* A = (g == 0) ? qin : (g == 1) ? kin : (g == 2) ? vin : (const float*)g_x;
    const __half* Wh = g_wblob + (size_t)g * 262144;

    const int tid  = threadIdx.x;
    const int lane = tid & 31;
    const int wid  = tid >> 5;
    const int wm   = (wid >> 2) * 32;
    const int wn   = (wid & 3) * 64;
    const int n0   = blockIdx.x * 256;
    const int m0   = blockIdx.y * 128;

    const int arow  = tid >> 2;
    const int acolf = (tid & 3) * 8;
    const int brow  = tid >> 1;
    const int bcolf = (tid & 1) * 16;

    const int a_lrow = (lane & 15);
    const int a_lcol = (lane >> 4) * 8;
    const int b_lrow = ((lane >> 4) << 3) + (lane & 7);
    const int b_lcol = ((lane >> 3) & 1) * 8;

    float acc[2][8][4];
    #pragma unroll
    for (int i = 0; i < 2; i++)
        #pragma unroll
        for (int j = 0; j < 8; j++)
            #pragma unroll
            for (int r = 0; r < 4; r++) acc[i][j][r] = 0.f;

    float4 rA[2];

    auto stageB = [&](int c, int st) {
        uint32_t dst = sb + (uint32_t)(st * STAGE_E + OFF_BH + brow * SAK + bcolf) * 2;
        const __half* src = Wh + (size_t)(n0 + brow) * DIMC + c * KC + bcolf;
        cp16(dst,      src);
        cp16(dst + 16, src + 8);
    };
    auto ldgA = [&](int c) {
        const float* src = A + (size_t)(m0 + arow) * DIMC + c * KC + acolf;
        rA[0] = __ldg((const float4*)src);
        rA[1] = __ldg((const float4*)(src + 4));
    };
    auto stsA = [&](int st) {
        __half* sAh = sm + st * STAGE_E + OFF_AH + arow * SAK + acolf;
        __half* sAl = sm + st * STAGE_E + OFF_AL + arow * SAK + acolf;
        #pragma unroll
        for (int u = 0; u < 2; u++) {
            float4 f = rA[u];
            __half h0 = __float2half_rn(f.x), h1 = __float2half_rn(f.y),
                   h2 = __float2half_rn(f.z), h3 = __float2half_rn(f.w);
            __half l0 = __float2half_rn(f.x - __half2float(h0));
            __half l1 = __float2half_rn(f.y - __half2float(h1));
            __half l2 = __float2half_rn(f.z - __half2float(h2));
            __half l3 = __float2half_rn(f.w - __half2float(h3));
            *(uint2*)(sAh + u * 4) = make_uint2(pack_h(h0, h1), pack_h(h2, h3));
            *(uint2*)(sAl + u * 4) = make_uint2(pack_h(l0, l1), pack_h(l2, l3));
        }
    };
    auto compute = [&](int st) {
        const uint32_t abase = sb + (uint32_t)(st * STAGE_E) * 2;
        #pragma unroll
        for (int ks = 0; ks < 2; ks++) {
            const int kc0 = ks * 16;
            uint32_t bf[8][2];
            uint32_t ah[2][4], al[2][4];
            #pragma unroll
            for (int i = 0; i < 2; i++) {
                uint32_t aaddr = abase + (uint32_t)(OFF_AH +
                    (wm + i * 16 + a_lrow) * SAK + kc0 + a_lcol) * 2;
                ldsm_x4(ah[i], aaddr);
                ldsm_x4(al[i], aaddr + (uint32_t)(OFF_AL - OFF_AH) * 2);
            }
            #pragma unroll
            for (int gg = 0; gg < 4; gg++) {
                uint32_t r[4];
                uint32_t addr = abase + (uint32_t)(OFF_BH +
                    (wn + gg * 16 + b_lrow) * SAK + kc0 + b_lcol) * 2;
                ldsm_x4(r, addr);
                bf[2 * gg][0] = r[0]; bf[2 * gg][1] = r[1];
                bf[2 * gg + 1][0] = r[2]; bf[2 * gg + 1][1] = r[3];
            }
            #pragma unroll
            for (int i = 0; i < 2; i++)
                #pragma unroll
                for (int j = 0; j < 8; j++)
                    mma16816(acc[i][j], ah[i], bf[j]);
            #pragma unroll
            for (int i = 0; i < 2; i++)
                #pragma unroll
                for (int j = 0; j < 8; j++)
                    mma16816(acc[i][j], al[i], bf[j]);
        }
    };

    stageB(0, 0);
    asm volatile("cp.async.commit_group;" ::: "memory");
    ldgA(0);
    stsA(0);

    for (int c = 0; c < 16; c++) {
        const int st  = c % 3;
        const int stn = (c + 1) % 3;
        if (c < 15) {
            ldgA(c + 1);
            stageB(c + 1, stn);
            asm volatile("cp.async.commit_group;" ::: "memory");
            asm volatile("cp.async.wait_group 1;" ::: "memory");
        } else {
            asm volatile("cp.async.wait_group 0;" ::: "memory");
        }
        __syncthreads();
        compute(st);
        if (c < 15) stsA(stn);
    }

    // ---- epilogue: mode-dependent stores ----
    #pragma unroll
    for (int j = 0; j < 8; j++) {
        int col = n0 + wn + j * 8 + (lane & 3) * 2;
        float bscale = (g == 0) ? SCALE_Q : 1.0f;
        float b0 = __ldg(bias + col) * bscale, b1 = __ldg(bias + col + 1) * bscale;
        #pragma unroll
        for (int i = 0; i < 2; i++) {
            int row = m0 + wm + i * 16 + (lane >> 2);
            float v00 = acc[i][j][0] + b0, v01 = acc[i][j][1] + b1;
            float v10 = acc[i][j][2] + b0, v11 = acc[i][j][3] + b1;
            if (g == 0) {
                __half h00 = __float2half_rn(v00), h01 = __float2half_rn(v01);
                __half h10 = __float2half_rn(v10), h11 = __float2half_rn(v11);
                *(uint32_t*)(g_qh + (size_t)row * DIMC + col)       = pack_h(h00, h01);
                *(uint32_t*)(g_qh + (size_t)(row + 8) * DIMC + col) = pack_h(h10, h11);
                *(uint32_t*)(g_ql + (size_t)row * DIMC + col) =
                    pack_h(__float2half_rn(v00 - __half2float(h00)),
                           __float2half_rn(v01 - __half2float(h01)));
                *(uint32_t*)(g_ql + (size_t)(row + 8) * DIMC + col) =
                    pack_h(__float2half_rn(v10 - __half2float(h10)),
                           __float2half_rn(v11 - __half2float(h11)));
            } else if (g == 1) {
                *(uint32_t*)(g_kh + (size_t)row * DIMC + col) =
                    pack_h(__float2half_rn(v00), __float2half_rn(v01));
                *(uint32_t*)(g_kh + (size_t)(row + 8) * DIMC + col) =
                    pack_h(__float2half_rn(v10), __float2half_rn(v11));
            } else if (g == 2) {
                // transposed: g_vt[(row/64)*32768 + col*64 + (row%64)]
                size_t base0 = (size_t)(row >> 6) * 32768 + (size_t)col * 64 + (row & 63);
                g_vt[base0]      = __float2half_rn(v00);
                g_vt[base0 + 64] = __float2half_rn(v01);
                int row1 = row + 8;
                size_t base1 = (size_t)(row1 >> 6) * 32768 + (size_t)col * 64 + (row1 & 63);
                g_vt[base1]      = __float2half_rn(v10);
                g_vt[base1 + 64] = __float2half_rn(v11);
            } else {
                *(float2*)(Cext + (size_t)row * DIMC + col) = make_float2(v00, v01);
                *(float2*)(Cext + (size_t)(row + 8) * DIMC + col) = make_float2(v10, v11);
            }
        }
    }
}

// ---------------------------------------------------------------------------
// Attention per (b,h): cp.async 4 ready fp16 tiles (Qh,Ql,Kh,Vt), S=QK^T,
// fp32 softmax, O=(Ph+Pl)V -> g_x fp32. No conversions, no transposes.
// ---------------------------------------------------------------------------
#define SK2   72
#define TQH   0
#define TQL   4608
#define TKH   9216
#define TVT   13824
#define OFF_S 36864
#define OFF_M 54272
#define SMEM_A 54528

__global__ __launch_bounds__(128, 4)
void attn(const int* __restrict__ mask) {
    extern __shared__ __half sha[];
    __half* sQh = sha + TQH;     // -> Ph after softmax
    __half* sQl = sha + TQL;     // -> Pl
    float*  sS  = (float*)((char*)sha + OFF_S);
    int*  smask = (int*)((char*)sha + OFF_M);
    const uint32_t sb = (uint32_t)__cvta_generic_to_shared(sha);

    const int blk  = blockIdx.x;
    const int h    = blk & (HEADS - 1);
    const int b    = blk >> 3;
    const int tid  = threadIdx.x;
    const int lane = tid & 31;
    const int wid  = tid >> 5;
    const int wm   = wid * 16;

    if (tid < NTOK) smask[tid] = mask[b * NTOK + tid];

    // ---- cp.async the 4 tiles: each 64 rows x 64 halves (128B/row) ----
    {
        // 512 segs of 16B per tile; 128 threads x 4 segs
        const __half* srcq = g_qh + (size_t)(b * 64) * DIMC + h * HD;
        const __half* srcl = g_ql + (size_t)(b * 64) * DIMC + h * HD;
        const __half* srck = g_kh + (size_t)(b * 64) * DIMC + h * HD;
        const __half* srcv = g_vt + (size_t)(b * 8 + h) * 4096;
        #pragma unroll
        for (int u = 0; u < 4; u++) {
            int seg = tid * 4 + u;
            int row = seg >> 3, s8 = (seg & 7) * 8;
            uint32_t dof = (uint32_t)(row * SK2 + s8) * 2;
            cp16(sb + (uint32_t)(TQH * 2) + dof, srcq + (size_t)row * DIMC + s8);
            cp16(sb + (uint32_t)(TQL * 2) + dof, srcl + (size_t)row * DIMC + s8);
            cp16(sb + (uint32_t)(TKH * 2) + dof, srck + (size_t)row * DIMC + s8);
            cp16(sb + (uint32_t)(TVT * 2) + dof, srcv + row * 64 + s8);
        }
        asm volatile("cp.async.commit_group;" ::: "memory");
        asm volatile("cp.async.wait_group 0;" ::: "memory");
    }
    __syncthreads();

    const int a_lrow = (lane & 15);
    const int a_lcol = (lane >> 4) * 8;
    const int b_lrow = ((lane >> 4) << 3) + (lane & 7);
    const int b_lcol = ((lane >> 3) & 1) * 8;

    // ---- S = (Qh+Ql) Kh^T ----
    {
        float acc[8][4];
        #pragma unroll
        for (int j = 0; j < 8; j++)
            #pragma unroll
            for (int r = 0; r < 4; r++) acc[j][r] = 0.f;
        #pragma unroll
        for (int ks = 0; ks < 4; ks++) {
            const int kc0 = ks * 16;
            uint32_t qh[4], ql[4], bf[8][2];
            uint32_t qaddr = sb + (uint32_t)(TQH + (wm + a_lrow) * SK2 + kc0 + a_lcol) * 2;
            ldsm_x4(qh, qaddr);
            ldsm_x4(ql, qaddr + (uint32_t)(TQL - TQH) * 2);
            #pragma unroll
            for (int gg = 0; gg < 4; gg++) {
                uint32_t r[4];
                ldsm_x4(r, sb + (uint32_t)(TKH + (gg * 16 + b_lrow) * SK2 + kc0 + b_lcol) * 2);
                bf[2 * gg][0] = r[0]; bf[2 * gg][1] = r[1];
                bf[2 * gg + 1][0] = r[2]; bf[2 * gg + 1][1] = r[3];
            }
            #pragma unroll
            for (int j = 0; j < 8; j++) mma16816(acc[j], qh, bf[j]);
            #pragma unroll
            for (int j = 0; j < 8; j++) mma16816(acc[j], ql, bf[j]);
        }
        #pragma unroll
        for (int j = 0; j < 8; j++) {
            int col = j * 8 + (lane & 3) * 2;
            int r0  = wm + (lane >> 2);
            sS[r0 * 68 + col]           = acc[j][0];
            sS[r0 * 68 + col + 1]       = acc[j][1];
            sS[(r0 + 8) * 68 + col]     = acc[j][2];
            sS[(r0 + 8) * 68 + col + 1] = acc[j][3];
        }
    }
    __syncthreads();

    // ---- masked softmax, write P hi/lo over Q tiles ----
    {
        const int row = tid >> 1;
        const int p   = tid & 1;
        float v[32];
        float m = -1e30f;
        #pragma unroll
        for (int s = 0; s < 32; s++) {
            int j = p * 32 + s;
            float sv = sS[row * 68 + j];
            v[s] = (smask[j] != 0) ? sv : -10000.0f;
            m = fmaxf(m, v[s]);
        }
        m = fmaxf(m, __shfl_xor_sync(0xffffffffu, m, 1));
        float sum = 0.f;
        #pragma unroll
        for (int s = 0; s < 32; s++) { v[s] = __expf(v[s] - m); sum += v[s]; }
        sum += __shfl_xor_sync(0xffffffffu, sum, 1);
        float inv = 1.0f / sum;
        #pragma unroll
        for (int s = 0; s < 32; s++) {
            int j = p * 32 + s;
            float pv = v[s] * inv;
            __half ph = __float2half_rn(pv);
            sQh[row * SK2 + j] = ph;
            sQl[row * SK2 + j] = __float2half_rn(pv - __half2float(ph));
        }
    }
    __syncthreads();

    // ---- O = (Ph+Pl) V ----
    {
        float acc[8][4];
        #pragma unroll
        for (int j = 0; j < 8; j++)
            #pragma unroll
            for (int r = 0; r < 4; r++) acc[j][r] = 0.f;
        #pragma unroll
        for (int ks = 0; ks < 4; ks++) {
            const int kc0 = ks * 16;
            uint32_t ph[4], pl[4], bf[8][2];
            uint32_t paddr = sb + (uint32_t)(TQH + (wm + a_lrow) * SK2 + kc0 + a_lcol) * 2;
            ldsm_x4(ph, paddr);
            ldsm_x4(pl, paddr + (uint32_t)(TQL - TQH) * 2);
            #pragma unroll
            for (int gg = 0; gg < 4; gg++) {
                uint32_t r[4];
                ldsm_x4(r, sb + (uint32_t)(TVT + (gg * 16 + b_lrow) * SK2 + kc0 + b_lcol) * 2);
                bf[2 * gg][0] = r[0]; bf[2 * gg][1] = r[1];
                bf[2 * gg + 1][0] = r[2]; bf[2 * gg + 1][1] = r[3];
            }
            #pragma unroll
            for (int j = 0; j < 8; j++) mma16816(acc[j], ph, bf[j]);
            #pragma unroll
            for (int j = 0; j < 8; j++) mma16816(acc[j], pl, bf[j]);
        }
        #pragma unroll
        for (int j = 0; j < 8; j++) {
            int col = h * HD + j * 8 + (lane & 3) * 2;
            int r0  = wm + (lane >> 2);
            *(float2*)(g_x + (size_t)(b * 64 + r0) * DIMC + col) =
                make_float2(acc[j][0], acc[j][1]);
            *(float2*)(g_x + (size_t)(b * 64 + r0 + 8) * DIMC + col) =
                make_float2(acc[j][2], acc[j][3]);
        }
    }
}

// ---------------------------------------------------------------------------
extern "C" void kernel_launch(void* const* d_in, const int* in_sizes, int n_in,
                              void* d_out, int out_size) {
    const float* q    = (const float*)d_in[0];
    const float* k    = (const float*)d_in[1];
    const float* v    = (const float*)d_in[2];
    const int*   mask = (const int*)  d_in[3];
    const float* Wq   = (const float*)d_in[4];
    const float* bq   = (const float*)d_in[5];
    const float* Wk   = (const float*)d_in[6];
    const float* bk   = (const float*)d_in[7];
    const float* Wv   = (const float*)d_in[8];
    const float* bv   = (const float*)d_in[9];
    const float* Wp   = (const float*)d_in[10];
    const float* bp   = (const float*)d_in[11];
    float* out = (float*)d_out;

    cudaFuncSetAttribute(gemm_mma, cudaFuncAttributeMaxDynamicSharedMemorySize, SMEM_G);
    cudaFuncSetAttribute(attn, cudaFuncAttributeMaxDynamicSharedMemorySize, SMEM_A);

    conv_w<<<4096, 256>>>(Wq, Wk, Wv, Wp);

    dim3 gg(DIMC / 256, MROWS / 128);
    gemm_mma<<<gg, 512, SMEM_G>>>(q, k, v, bq, nullptr, 0);
    gemm_mma<<<gg, 512, SMEM_G>>>(q, k, v, bk, nullptr, 1);
    gemm_mma<<<gg, 512, SMEM_G>>>(q, k, v, bv, nullptr, 2);

    attn<<<BATCH * HEADS, 128, SMEM_A>>>(mask);

    gemm_mma<<<gg, 512, SMEM_G>>>(q, k, v, bp, out, 3);
}

// round 13
// speedup vs baseline: 1.2157x; 1.1568x over previous
#include <cuda_runtime.h>
#include <cuda_fp16.h>
#include <cstdint>

#define DIMC   512
#define HEADS  8
#define HD     64
#define NTOK   64
#define BATCH  2048
#define MROWS  (BATCH * NTOK)     // 131072
#define SCALE_Q 0.125f

// ---------------- device scratch ----------------
__device__ __half g_qh[(size_t)MROWS * DIMC];   // Q hi (scale folded)
__device__ __half g_ql[(size_t)MROWS * DIMC];   // Q lo
__device__ __half g_kh[(size_t)MROWS * DIMC];   // K hi
__device__ __half g_vt[(size_t)MROWS * DIMC];   // V hi, transposed [b][h][d][token]
__device__ __half g_xh[(size_t)MROWS * DIMC];   // attn out (fp16)
__device__ __align__(128) __half g_wblob[(size_t)4 * 512 * 512];

// ---------------------------------------------------------------------------
// Kernel 0: weights -> fp16 blobs. Wq pre-scaled by SCALE_Q (exact pow2).
// ---------------------------------------------------------------------------
__global__ void conv_w(const float* __restrict__ Wq, const float* __restrict__ Wk,
                       const float* __restrict__ Wv, const float* __restrict__ Wp) {
    int idx = blockIdx.x * 256 + threadIdx.x;
    int g   = idx >> 18;
    int rem = idx & 262143;
    const float* W = (g == 0) ? Wq : (g == 1) ? Wk : (g == 2) ? Wv : Wp;
    float w = W[rem] * ((g == 0) ? SCALE_Q : 1.0f);
    g_wblob[(size_t)g * 262144 + rem] = __float2half_rn(w);
}

// ---------------------------------------------------------------------------
// common MMA helpers
// ---------------------------------------------------------------------------
__device__ __forceinline__ void mma16816(float* d, const uint32_t* a, const uint32_t* b) {
    asm volatile(
        "mma.sync.aligned.m16n8k16.row.col.f32.f16.f16.f32 "
        "{%0,%1,%2,%3}, {%4,%5,%6,%7}, {%8,%9}, {%0,%1,%2,%3};"
        : "+f"(d[0]), "+f"(d[1]), "+f"(d[2]), "+f"(d[3])
        : "r"(a[0]), "r"(a[1]), "r"(a[2]), "r"(a[3]), "r"(b[0]), "r"(b[1]));
}
__device__ __forceinline__ void ldsm_x4(uint32_t* r, uint32_t addr) {
    asm volatile("ldmatrix.sync.aligned.m8n8.x4.shared.b16 {%0,%1,%2,%3}, [%4];"
        : "=r"(r[0]), "=r"(r[1]), "=r"(r[2]), "=r"(r[3]) : "r"(addr));
}
__device__ __forceinline__ void cp16(uint32_t dst, const void* src) {
    asm volatile("cp.async.cg.shared.global [%0], [%1], 16;" :: "r"(dst), "l"(src));
}
__device__ __forceinline__ uint32_t pack_h(__half a, __half b) {
    return (uint32_t)__half_as_ushort(a) | ((uint32_t)__half_as_ushort(b) << 16);
}

// ---------------------------------------------------------------------------
// Fused QKV GEMM (one launch, grid.z = g): fp16 hi/lo 2-product, KC=32.
// Epilogues: 0=Q->hi/lo fp16, 1=K->fp16, 2=V->fp16 transposed.
// ---------------------------------------------------------------------------
#define KC      32
#define SAK     40
#define OFF_AH  0
#define OFF_AL  (128 * SAK)
#define OFF_BH  (2 * 128 * SAK)
#define STAGE_E (2 * 128 * SAK + 256 * SAK)
#define SMEM_G  (3 * STAGE_E * 2)

__global__ __launch_bounds__(512, 1)
void gemm_qkv(const float* __restrict__ qin, const float* __restrict__ kin,
              const float* __restrict__ vin,
              const float* __restrict__ bq, const float* __restrict__ bk,
              const float* __restrict__ bv) {
    extern __shared__ __half sm[];
    const uint32_t sb = (uint32_t)__cvta_generic_to_shared(sm);

    const int g = blockIdx.z;
    const float* A    = (g == 0) ? qin : (g == 1) ? kin : vin;
    const float* bias = (g == 0) ? bq  : (g == 1) ? bk  : bv;
    const __half* Wh  = g_wblob + (size_t)g * 262144;

    const int tid  = threadIdx.x;
    const int lane = tid & 31;
    const int wid  = tid >> 5;
    const int wm   = (wid >> 2) * 32;
    const int wn   = (wid & 3) * 64;
    const int n0   = blockIdx.x * 256;
    const int m0   = blockIdx.y * 128;

    const int arow  = tid >> 2;
    const int acolf = (tid & 3) * 8;
    const int brow  = tid >> 1;
    const int bcolf = (tid & 1) * 16;

    const int a_lrow = (lane & 15);
    const int a_lcol = (lane >> 4) * 8;
    const int b_lrow = ((lane >> 4) << 3) + (lane & 7);
    const int b_lcol = ((lane >> 3) & 1) * 8;

    float acc[2][8][4];
    #pragma unroll
    for (int i = 0; i < 2; i++)
        #pragma unroll
        for (int j = 0; j < 8; j++)
            #pragma unroll
            for (int r = 0; r < 4; r++) acc[i][j][r] = 0.f;

    float4 rA[2];

    auto stageB = [&](int c, int st) {
        uint32_t dst = sb + (uint32_t)(st * STAGE_E + OFF_BH + brow * SAK + bcolf) * 2;
        const __half* src = Wh + (size_t)(n0 + brow) * DIMC + c * KC + bcolf;
        cp16(dst,      src);
        cp16(dst + 16, src + 8);
    };
    auto ldgA = [&](int c) {
        const float* src = A + (size_t)(m0 + arow) * DIMC + c * KC + acolf;
        rA[0] = __ldg((const float4*)src);
        rA[1] = __ldg((const float4*)(src + 4));
    };
    auto stsA = [&](int st) {
        __half* sAh = sm + st * STAGE_E + OFF_AH + arow * SAK + acolf;
        __half* sAl = sm + st * STAGE_E + OFF_AL + arow * SAK + acolf;
        #pragma unroll
        for (int u = 0; u < 2; u++) {
            float4 f = rA[u];
            __half h0 = __float2half_rn(f.x), h1 = __float2half_rn(f.y),
                   h2 = __float2half_rn(f.z), h3 = __float2half_rn(f.w);
            __half l0 = __float2half_rn(f.x - __half2float(h0));
            __half l1 = __float2half_rn(f.y - __half2float(h1));
            __half l2 = __float2half_rn(f.z - __half2float(h2));
            __half l3 = __float2half_rn(f.w - __half2float(h3));
            *(uint2*)(sAh + u * 4) = make_uint2(pack_h(h0, h1), pack_h(h2, h3));
            *(uint2*)(sAl + u * 4) = make_uint2(pack_h(l0, l1), pack_h(l2, l3));
        }
    };
    auto compute = [&](int st) {
        const uint32_t abase = sb + (uint32_t)(st * STAGE_E) * 2;
        #pragma unroll
        for (int ks = 0; ks < 2; ks++) {
            const int kc0 = ks * 16;
            uint32_t bf[8][2];
            uint32_t ah[2][4], al[2][4];
            #pragma unroll
            for (int i = 0; i < 2; i++) {
                uint32_t aaddr = abase + (uint32_t)(OFF_AH +
                    (wm + i * 16 + a_lrow) * SAK + kc0 + a_lcol) * 2;
                ldsm_x4(ah[i], aaddr);
                ldsm_x4(al[i], aaddr + (uint32_t)(OFF_AL - OFF_AH) * 2);
            }
            #pragma unroll
            for (int gg = 0; gg < 4; gg++) {
                uint32_t r[4];
                uint32_t addr = abase + (uint32_t)(OFF_BH +
                    (wn + gg * 16 + b_lrow) * SAK + kc0 + b_lcol) * 2;
                ldsm_x4(r, addr);
                bf[2 * gg][0] = r[0]; bf[2 * gg][1] = r[1];
                bf[2 * gg + 1][0] = r[2]; bf[2 * gg + 1][1] = r[3];
            }
            #pragma unroll
            for (int i = 0; i < 2; i++)
                #pragma unroll
                for (int j = 0; j < 8; j++)
                    mma16816(acc[i][j], ah[i], bf[j]);
            #pragma unroll
            for (int i = 0; i < 2; i++)
                #pragma unroll
                for (int j = 0; j < 8; j++)
                    mma16816(acc[i][j], al[i], bf[j]);
        }
    };

    stageB(0, 0);
    asm volatile("cp.async.commit_group;" ::: "memory");
    ldgA(0);
    stsA(0);

    for (int c = 0; c < 16; c++) {
        const int st  = c % 3;
        const int stn = (c + 1) % 3;
        if (c < 15) {
            ldgA(c + 1);
            stageB(c + 1, stn);
            asm volatile("cp.async.commit_group;" ::: "memory");
            asm volatile("cp.async.wait_group 1;" ::: "memory");
        } else {
            asm volatile("cp.async.wait_group 0;" ::: "memory");
        }
        __syncthreads();
        compute(st);
        if (c < 15) stsA(stn);
    }

    // ---- epilogue per g ----
    #pragma unroll
    for (int j = 0; j < 8; j++) {
        int col = n0 + wn + j * 8 + (lane & 3) * 2;
        float bscale = (g == 0) ? SCALE_Q : 1.0f;
        float b0 = __ldg(bias + col) * bscale, b1 = __ldg(bias + col + 1) * bscale;
        #pragma unroll
        for (int i = 0; i < 2; i++) {
            int row = m0 + wm + i * 16 + (lane >> 2);
            float v00 = acc[i][j][0] + b0, v01 = acc[i][j][1] + b1;
            float v10 = acc[i][j][2] + b0, v11 = acc[i][j][3] + b1;
            if (g == 0) {
                __half h00 = __float2half_rn(v00), h01 = __float2half_rn(v01);
                __half h10 = __float2half_rn(v10), h11 = __float2half_rn(v11);
                *(uint32_t*)(g_qh + (size_t)row * DIMC + col)       = pack_h(h00, h01);
                *(uint32_t*)(g_qh + (size_t)(row + 8) * DIMC + col) = pack_h(h10, h11);
                *(uint32_t*)(g_ql + (size_t)row * DIMC + col) =
                    pack_h(__float2half_rn(v00 - __half2float(h00)),
                           __float2half_rn(v01 - __half2float(h01)));
                *(uint32_t*)(g_ql + (size_t)(row + 8) * DIMC + col) =
                    pack_h(__float2half_rn(v10 - __half2float(h10)),
                           __float2half_rn(v11 - __half2float(h11)));
            } else if (g == 1) {
                *(uint32_t*)(g_kh + (size_t)row * DIMC + col) =
                    pack_h(__float2half_rn(v00), __float2half_rn(v01));
                *(uint32_t*)(g_kh + (size_t)(row + 8) * DIMC + col) =
                    pack_h(__float2half_rn(v10), __float2half_rn(v11));
            } else {
                size_t base0 = (size_t)(row >> 6) * 32768 + (size_t)col * 64 + (row & 63);
                g_vt[base0]      = __float2half_rn(v00);
                g_vt[base0 + 64] = __float2half_rn(v01);
                int row1 = row + 8;
                size_t base1 = (size_t)(row1 >> 6) * 32768 + (size_t)col * 64 + (row1 & 63);
                g_vt[base1]      = __float2half_rn(v10);
                g_vt[base1 + 64] = __float2half_rn(v11);
            }
        }
    }
}

// ---------------------------------------------------------------------------
// Proj GEMM: out = g_xh(fp16) @ Wp^T + bp. Single-pass fp16 MMA, all-cp.async
// staging (A and B preconverted). Half the MMA work of the QKV GEMMs.
// ---------------------------------------------------------------------------
#define POFF_A  0
#define POFF_B  (128 * SAK)
#define PSTAGE  (128 * SAK + 256 * SAK)           // 15360 halves
#define SMEM_P  (3 * PSTAGE * 2)                   // 92160 bytes

__global__ __launch_bounds__(512, 1)
void gemm_proj(const float* __restrict__ bias, float* __restrict__ out) {
    extern __shared__ __half sm[];
    const uint32_t sb = (uint32_t)__cvta_generic_to_shared(sm);
    const __half* Wh = g_wblob + (size_t)3 * 262144;

    const int tid  = threadIdx.x;
    const int lane = tid & 31;
    const int wid  = tid >> 5;
    const int wm   = (wid >> 2) * 32;
    const int wn   = (wid & 3) * 64;
    const int n0   = blockIdx.x * 256;
    const int m0   = blockIdx.y * 128;

    // A staging: 4 threads per row, 8 halves (16B) each
    const int arow  = tid >> 2;
    const int acolf = (tid & 3) * 8;
    // B staging: 2 threads per row, 16 halves each
    const int brow  = tid >> 1;
    const int bcolf = (tid & 1) * 16;

    const int a_lrow = (lane & 15);
    const int a_lcol = (lane >> 4) * 8;
    const int b_lrow = ((lane >> 4) << 3) + (lane & 7);
    const int b_lcol = ((lane >> 3) & 1) * 8;

    float acc[2][8][4];
    #pragma unroll
    for (int i = 0; i < 2; i++)
        #pragma unroll
        for (int j = 0; j < 8; j++)
            #pragma unroll
            for (int r = 0; r < 4; r++) acc[i][j][r] = 0.f;

    auto stage = [&](int c, int st) {
        uint32_t dA = sb + (uint32_t)(st * PSTAGE + POFF_A + arow * SAK + acolf) * 2;
        cp16(dA, g_xh + (size_t)(m0 + arow) * DIMC + c * KC + acolf);
        uint32_t dB = sb + (uint32_t)(st * PSTAGE + POFF_B + brow * SAK + bcolf) * 2;
        const __half* srcB = Wh + (size_t)(n0 + brow) * DIMC + c * KC + bcolf;
        cp16(dB,      srcB);
        cp16(dB + 16, srcB + 8);
    };
    auto compute = [&](int st) {
        const uint32_t abase = sb + (uint32_t)(st * PSTAGE) * 2;
        #pragma unroll
        for (int ks = 0; ks < 2; ks++) {
            const int kc0 = ks * 16;
            uint32_t bf[8][2];
            uint32_t ah[2][4];
            #pragma unroll
            for (int i = 0; i < 2; i++) {
                ldsm_x4(ah[i], abase + (uint32_t)(POFF_A +
                    (wm + i * 16 + a_lrow) * SAK + kc0 + a_lcol) * 2);
            }
            #pragma unroll
            for (int gg = 0; gg < 4; gg++) {
                uint32_t r[4];
                ldsm_x4(r, abase + (uint32_t)(POFF_B +
                    (wn + gg * 16 + b_lrow) * SAK + kc0 + b_lcol) * 2);
                bf[2 * gg][0] = r[0]; bf[2 * gg][1] = r[1];
                bf[2 * gg + 1][0] = r[2]; bf[2 * gg + 1][1] = r[3];
            }
            #pragma unroll
            for (int i = 0; i < 2; i++)
                #pragma unroll
                for (int j = 0; j < 8; j++)
                    mma16816(acc[i][j], ah[i], bf[j]);
        }
    };

    stage(0, 0);
    asm volatile("cp.async.commit_group;" ::: "memory");

    for (int c = 0; c < 16; c++) {
        const int st  = c % 3;
        const int stn = (c + 1) % 3;
        if (c < 15) {
            stage(c + 1, stn);
            asm volatile("cp.async.commit_group;" ::: "memory");
            asm volatile("cp.async.wait_group 1;" ::: "memory");
        } else {
            asm volatile("cp.async.wait_group 0;" ::: "memory");
        }
        __syncthreads();
        compute(st);
    }

    #pragma unroll
    for (int j = 0; j < 8; j++) {
        int col = n0 + wn + j * 8 + (lane & 3) * 2;
        float b0 = __ldg(bias + col), b1 = __ldg(bias + col + 1);
        #pragma unroll
        for (int i = 0; i < 2; i++) {
            int row = m0 + wm + i * 16 + (lane >> 2);
            *(float2*)(out + (size_t)row * DIMC + col) =
                make_float2(acc[i][j][0] + b0, acc[i][j][1] + b1);
            *(float2*)(out + (size_t)(row + 8) * DIMC + col) =
                make_float2(acc[i][j][2] + b0, acc[i][j][3] + b1);
        }
    }
}

// ---------------------------------------------------------------------------
// Attention per (b,h): cp.async 4 fp16 tiles, S=QK^T, fp32 softmax,
// O=(Ph+Pl)V -> g_xh fp16.
// ---------------------------------------------------------------------------
#define SK2   72
#define TQH   0
#define TQL   4608
#define TKH   9216
#define TVT   13824
#define OFF_S 36864
#define OFF_M 54272
#define SMEM_A 54528

__global__ __launch_bounds__(128, 4)
void attn(const int* __restrict__ mask) {
    extern __shared__ __half sha[];
    __half* sQh = sha + TQH;
    __half* sQl = sha + TQL;
    float*  sS  = (float*)((char*)sha + OFF_S);
    int*  smask = (int*)((char*)sha + OFF_M);
    const uint32_t sb = (uint32_t)__cvta_generic_to_shared(sha);

    const int blk  = blockIdx.x;
    const int h    = blk & (HEADS - 1);
    const int b    = blk >> 3;
    const int tid  = threadIdx.x;
    const int lane = tid & 31;
    const int wid  = tid >> 5;
    const int wm   = wid * 16;

    if (tid < NTOK) smask[tid] = mask[b * NTOK + tid];

    {
        const __half* srcq = g_qh + (size_t)(b * 64) * DIMC + h * HD;
        const __half* srcl = g_ql + (size_t)(b * 64) * DIMC + h * HD;
        const __half* srck = g_kh + (size_t)(b * 64) * DIMC + h * HD;
        const __half* srcv = g_vt + (size_t)(b * 8 + h) * 4096;
        #pragma unroll
        for (int u = 0; u < 4; u++) {
            int seg = tid * 4 + u;
            int row = seg >> 3, s8 = (seg & 7) * 8;
            uint32_t dof = (uint32_t)(row * SK2 + s8) * 2;
            cp16(sb + (uint32_t)(TQH * 2) + dof, srcq + (size_t)row * DIMC + s8);
            cp16(sb + (uint32_t)(TQL * 2) + dof, srcl + (size_t)row * DIMC + s8);
            cp16(sb + (uint32_t)(TKH * 2) + dof, srck + (size_t)row * DIMC + s8);
            cp16(sb + (uint32_t)(TVT * 2) + dof, srcv + row * 64 + s8);
        }
        asm volatile("cp.async.commit_group;" ::: "memory");
        asm volatile("cp.async.wait_group 0;" ::: "memory");
    }
    __syncthreads();

    const int a_lrow = (lane & 15);
    const int a_lcol = (lane >> 4) * 8;
    const int b_lrow = ((lane >> 4) << 3) + (lane & 7);
    const int b_lcol = ((lane >> 3) & 1) * 8;

    {
        float acc[8][4];
        #pragma unroll
        for (int j = 0; j < 8; j++)
            #pragma unroll
            for (int r = 0; r < 4; r++) acc[j][r] = 0.f;
        #pragma unroll
        for (int ks = 0; ks < 4; ks++) {
            const int kc0 = ks * 16;
            uint32_t qh[4], ql[4], bf[8][2];
            uint32_t qaddr = sb + (uint32_t)(TQH + (wm + a_lrow) * SK2 + kc0 + a_lcol) * 2;
            ldsm_x4(qh, qaddr);
            ldsm_x4(ql, qaddr + (uint32_t)(TQL - TQH) * 2);
            #pragma unroll
            for (int gg = 0; gg < 4; gg++) {
                uint32_t r[4];
                ldsm_x4(r, sb + (uint32_t)(TKH + (gg * 16 + b_lrow) * SK2 + kc0 + b_lcol) * 2);
                bf[2 * gg][0] = r[0]; bf[2 * gg][1] = r[1];
                bf[2 * gg + 1][0] = r[2]; bf[2 * gg + 1][1] = r[3];
            }
            #pragma unroll
            for (int j = 0; j < 8; j++) mma16816(acc[j], qh, bf[j]);
            #pragma unroll
            for (int j = 0; j < 8; j++) mma16816(acc[j], ql, bf[j]);
        }
        #pragma unroll
        for (int j = 0; j < 8; j++) {
            int col = j * 8 + (lane & 3) * 2;
            int r0  = wm + (lane >> 2);
            sS[r0 * 68 + col]           = acc[j][0];
            sS[r0 * 68 + col + 1]       = acc[j][1];
            sS[(r0 + 8) * 68 + col]     = acc[j][2];
            sS[(r0 + 8) * 68 + col + 1] = acc[j][3];
        }
    }
    __syncthreads();

    {
        const int row = tid >> 1;
        const int p   = tid & 1;
        float v[32];
        float m = -1e30f;
        #pragma unroll
        for (int s = 0; s < 32; s++) {
            int j = p * 32 + s;
            float sv = sS[row * 68 + j];
            v[s] = (smask[j] != 0) ? sv : -10000.0f;
            m = fmaxf(m, v[s]);
        }
        m = fmaxf(m, __shfl_xor_sync(0xffffffffu, m, 1));
        float sum = 0.f;
        #pragma unroll
        for (int s = 0; s < 32; s++) { v[s] = __expf(v[s] - m); sum += v[s]; }
        sum += __shfl_xor_sync(0xffffffffu, sum, 1);
        float inv = 1.0f / sum;
        #pragma unroll
        for (int s = 0; s < 32; s++) {
            int j = p * 32 + s;
            float pv = v[s] * inv;
            __half ph = __float2half_rn(pv);
            sQh[row * SK2 + j] = ph;
            sQl[row * SK2 + j] = __float2half_rn(pv - __half2float(ph));
        }
    }
    __syncthreads();

    {
        float acc[8][4];
        #pragma unroll
        for (int j = 0; j < 8; j++)
            #pragma unroll
            for (int r = 0; r < 4; r++) acc[j][r] = 0.f;
        #pragma unroll
        for (int ks = 0; ks < 4; ks++) {
            const int kc0 = ks * 16;
            uint32_t ph[4], pl[4], bf[8][2];
            uint32_t paddr = sb + (uint32_t)(TQH + (wm + a_lrow) * SK2 + kc0 + a_lcol) * 2;
            ldsm_x4(ph, paddr);
            ldsm_x4(pl, paddr + (uint32_t)(TQL - TQH) * 2);
            #pragma unroll
            for (int gg = 0; gg < 4; gg++) {
                uint32_t r[4];
                ldsm_x4(r, sb + (uint32_t)(TVT + (gg * 16 + b_lrow) * SK2 + kc0 + b_lcol) * 2);
                bf[2 * gg][0] = r[0]; bf[2 * gg][1] = r[1];
                bf[2 * gg + 1][0] = r[2]; bf[2 * gg + 1][1] = r[3];
            }
            #pragma unroll
            for (int j = 0; j < 8; j++) mma16816(acc[j], ph, bf[j]);
            #pragma unroll
            for (int j = 0; j < 8; j++) mma16816(acc[j], pl, bf[j]);
        }
        #pragma unroll
        for (int j = 0; j < 8; j++) {
            int col = h * HD + j * 8 + (lane & 3) * 2;
            int r0  = wm + (lane >> 2);
            *(uint32_t*)(g_xh + (size_t)(b * 64 + r0) * DIMC + col) =
                pack_h(__float2half_rn(acc[j][0]), __float2half_rn(acc[j][1]));
            *(uint32_t*)(g_xh + (size_t)(b * 64 + r0 + 8) * DIMC + col) =
                pack_h(__float2half_rn(acc[j][2]), __float2half_rn(acc[j][3]));
        }
    }
}

// ---------------------------------------------------------------------------
extern "C" void kernel_launch(void* const* d_in, const int* in_sizes, int n_in,
                              void* d_out, int out_size) {
    const float* q    = (const float*)d_in[0];
    const float* k    = (const float*)d_in[1];
    const float* v    = (const float*)d_in[2];
    const int*   mask = (const int*)  d_in[3];
    const float* Wq   = (const float*)d_in[4];
    const float* bq   = (const float*)d_in[5];
    const float* Wk   = (const float*)d_in[6];
    const float* bk   = (const float*)d_in[7];
    const float* Wv   = (const float*)d_in[8];
    const float* bv   = (const float*)d_in[9];
    const float* Wp   = (const float*)d_in[10];
    const float* bp   = (const float*)d_in[11];
    float* out = (float*)d_out;

    cudaFuncSetAttribute(gemm_qkv,  cudaFuncAttributeMaxDynamicSharedMemorySize, SMEM_G);
    cudaFuncSetAttribute(gemm_proj, cudaFuncAttributeMaxDynamicSharedMemorySize, SMEM_P);
    cudaFuncSetAttribute(attn,      cudaFuncAttributeMaxDynamicSharedMemorySize, SMEM_A);

    conv_w<<<4096, 256>>>(Wq, Wk, Wv, Wp);

    dim3 gqkv(DIMC / 256, MROWS / 128, 3);
    gemm_qkv<<<gqkv, 512, SMEM_G>>>(q, k, v, bq, bk, bv);

    attn<<<BATCH * HEADS, 128, SMEM_A>>>(mask);

    dim3 gp(DIMC / 256, MROWS / 128);
    gemm_proj<<<gp, 512, SMEM_P>>>(bp, out);
}

// round 14
// speedup vs baseline: 1.5192x; 1.2497x over previous
#include <cuda_runtime.h>
#include <cuda_fp16.h>
#include <cstdint>

#define DIMC   512
#define HEADS  8
#define HD     64
#define NTOK   64
#define BATCH  2048
#define MROWS  (BATCH * NTOK)     // 131072
#define SCALE_Q 0.125f

// ---------------- device scratch ----------------
__device__ __half g_qh[(size_t)MROWS * DIMC];   // Q hi (scale folded)
__device__ __half g_ql[(size_t)MROWS * DIMC];   // Q lo
__device__ __half g_kh[(size_t)MROWS * DIMC];   // K hi
__device__ __half g_vt[(size_t)MROWS * DIMC];   // V hi, transposed [b][h][d][token]
__device__ __half g_xh[(size_t)MROWS * DIMC];   // attn out (fp16)
__device__ __align__(128) __half g_wblob[(size_t)4 * 512 * 512];

// ---------------------------------------------------------------------------
// Kernel 0: weights -> fp16 blobs. Wq pre-scaled by SCALE_Q (exact pow2).
// ---------------------------------------------------------------------------
__global__ void conv_w(const float* __restrict__ Wq, const float* __restrict__ Wk,
                       const float* __restrict__ Wv, const float* __restrict__ Wp) {
    int idx = blockIdx.x * 256 + threadIdx.x;
    int g   = idx >> 18;
    int rem = idx & 262143;
    const float* W = (g == 0) ? Wq : (g == 1) ? Wk : (g == 2) ? Wv : Wp;
    float w = W[rem] * ((g == 0) ? SCALE_Q : 1.0f);
    g_wblob[(size_t)g * 262144 + rem] = __float2half_rn(w);
}

// ---------------------------------------------------------------------------
// common MMA helpers
// ---------------------------------------------------------------------------
__device__ __forceinline__ void mma16816(float* d, const uint32_t* a, const uint32_t* b) {
    asm volatile(
        "mma.sync.aligned.m16n8k16.row.col.f32.f16.f16.f32 "
        "{%0,%1,%2,%3}, {%4,%5,%6,%7}, {%8,%9}, {%0,%1,%2,%3};"
        : "+f"(d[0]), "+f"(d[1]), "+f"(d[2]), "+f"(d[3])
        : "r"(a[0]), "r"(a[1]), "r"(a[2]), "r"(a[3]), "r"(b[0]), "r"(b[1]));
}
__device__ __forceinline__ void ldsm_x4(uint32_t* r, uint32_t addr) {
    asm volatile("ldmatrix.sync.aligned.m8n8.x4.shared.b16 {%0,%1,%2,%3}, [%4];"
        : "=r"(r[0]), "=r"(r[1]), "=r"(r[2]), "=r"(r[3]) : "r"(addr));
}
__device__ __forceinline__ void cp16(uint32_t dst, const void* src) {
    asm volatile("cp.async.cg.shared.global [%0], [%1], 16;" :: "r"(dst), "l"(src));
}
__device__ __forceinline__ uint32_t pack_h(__half a, __half b) {
    return (uint32_t)__half_as_ushort(a) | ((uint32_t)__half_as_ushort(b) << 16);
}

// ---------------------------------------------------------------------------
// Fused QKV GEMM (grid.z = g): SINGLE-PASS fp16 (inputs quantized to fp16 at
// staging). Epilogues: 0=Q->hi/lo fp16 (from fp32 acc), 1=K->fp16, 2=V->fp16^T.
// ---------------------------------------------------------------------------
#define KC      32
#define SAK     40
#define OFF_A   0
#define OFF_B   (128 * SAK)
#define STAGE_E (128 * SAK + 256 * SAK)           // 15360 halves
#define SMEM_G  (3 * STAGE_E * 2)                  // 92160 bytes

__global__ __launch_bounds__(512, 1)
void gemm_qkv(const float* __restrict__ qin, const float* __restrict__ kin,
              const float* __restrict__ vin,
              const float* __restrict__ bq, const float* __restrict__ bk,
              const float* __restrict__ bv) {
    extern __shared__ __half sm[];
    const uint32_t sb = (uint32_t)__cvta_generic_to_shared(sm);

    const int g = blockIdx.z;
    const float* A    = (g == 0) ? qin : (g == 1) ? kin : vin;
    const float* bias = (g == 0) ? bq  : (g == 1) ? bk  : bv;
    const __half* Wh  = g_wblob + (size_t)g * 262144;

    const int tid  = threadIdx.x;
    const int lane = tid & 31;
    const int wid  = tid >> 5;
    const int wm   = (wid >> 2) * 32;
    const int wn   = (wid & 3) * 64;
    const int n0   = blockIdx.x * 256;
    const int m0   = blockIdx.y * 128;

    const int arow  = tid >> 2;
    const int acolf = (tid & 3) * 8;
    const int brow  = tid >> 1;
    const int bcolf = (tid & 1) * 16;

    const int a_lrow = (lane & 15);
    const int a_lcol = (lane >> 4) * 8;
    const int b_lrow = ((lane >> 4) << 3) + (lane & 7);
    const int b_lcol = ((lane >> 3) & 1) * 8;

    float acc[2][8][4];
    #pragma unroll
    for (int i = 0; i < 2; i++)
        #pragma unroll
        for (int j = 0; j < 8; j++)
            #pragma unroll
            for (int r = 0; r < 4; r++) acc[i][j][r] = 0.f;

    float4 rA[2];

    auto stageB = [&](int c, int st) {
        uint32_t dst = sb + (uint32_t)(st * STAGE_E + OFF_B + brow * SAK + bcolf) * 2;
        const __half* src = Wh + (size_t)(n0 + brow) * DIMC + c * KC + bcolf;
        cp16(dst,      src);
        cp16(dst + 16, src + 8);
    };
    auto ldgA = [&](int c) {
        const float* src = A + (size_t)(m0 + arow) * DIMC + c * KC + acolf;
        rA[0] = __ldg((const float4*)src);
        rA[1] = __ldg((const float4*)(src + 4));
    };
    auto stsA = [&](int st) {
        __half* sA = sm + st * STAGE_E + OFF_A + arow * SAK + acolf;
        #pragma unroll
        for (int u = 0; u < 2; u++) {
            float4 f = rA[u];
            *(uint2*)(sA + u * 4) = make_uint2(
                pack_h(__float2half_rn(f.x), __float2half_rn(f.y)),
                pack_h(__float2half_rn(f.z), __float2half_rn(f.w)));
        }
    };
    auto compute = [&](int st) {
        const uint32_t abase = sb + (uint32_t)(st * STAGE_E) * 2;
        #pragma unroll
        for (int ks = 0; ks < 2; ks++) {
            const int kc0 = ks * 16;
            uint32_t bf[8][2];
            uint32_t ah[2][4];
            #pragma unroll
            for (int i = 0; i < 2; i++) {
                ldsm_x4(ah[i], abase + (uint32_t)(OFF_A +
                    (wm + i * 16 + a_lrow) * SAK + kc0 + a_lcol) * 2);
            }
            #pragma unroll
            for (int gg = 0; gg < 4; gg++) {
                uint32_t r[4];
                ldsm_x4(r, abase + (uint32_t)(OFF_B +
                    (wn + gg * 16 + b_lrow) * SAK + kc0 + b_lcol) * 2);
                bf[2 * gg][0] = r[0]; bf[2 * gg][1] = r[1];
                bf[2 * gg + 1][0] = r[2]; bf[2 * gg + 1][1] = r[3];
            }
            #pragma unroll
            for (int i = 0; i < 2; i++)
                #pragma unroll
                for (int j = 0; j < 8; j++)
                    mma16816(acc[i][j], ah[i], bf[j]);
        }
    };

    stageB(0, 0);
    asm volatile("cp.async.commit_group;" ::: "memory");
    ldgA(0);
    stsA(0);

    for (int c = 0; c < 16; c++) {
        const int st  = c % 3;
        const int stn = (c + 1) % 3;
        if (c < 15) {
            ldgA(c + 1);
            stageB(c + 1, stn);
            asm volatile("cp.async.commit_group;" ::: "memory");
            asm volatile("cp.async.wait_group 1;" ::: "memory");
        } else {
            asm volatile("cp.async.wait_group 0;" ::: "memory");
        }
        __syncthreads();
        compute(st);
        if (c < 15) stsA(stn);
    }

    // ---- epilogue per g ----
    #pragma unroll
    for (int j = 0; j < 8; j++) {
        int col = n0 + wn + j * 8 + (lane & 3) * 2;
        float bscale = (g == 0) ? SCALE_Q : 1.0f;
        float b0 = __ldg(bias + col) * bscale, b1 = __ldg(bias + col + 1) * bscale;
        #pragma unroll
        for (int i = 0; i < 2; i++) {
            int row = m0 + wm + i * 16 + (lane >> 2);
            float v00 = acc[i][j][0] + b0, v01 = acc[i][j][1] + b1;
            float v10 = acc[i][j][2] + b0, v11 = acc[i][j][3] + b1;
            if (g == 0) {
                __half h00 = __float2half_rn(v00), h01 = __float2half_rn(v01);
                __half h10 = __float2half_rn(v10), h11 = __float2half_rn(v11);
                *(uint32_t*)(g_qh + (size_t)row * DIMC + col)       = pack_h(h00, h01);
                *(uint32_t*)(g_qh + (size_t)(row + 8) * DIMC + col) = pack_h(h10, h11);
                *(uint32_t*)(g_ql + (size_t)row * DIMC + col) =
                    pack_h(__float2half_rn(v00 - __half2float(h00)),
                           __float2half_rn(v01 - __half2float(h01)));
                *(uint32_t*)(g_ql + (size_t)(row + 8) * DIMC + col) =
                    pack_h(__float2half_rn(v10 - __half2float(h10)),
                           __float2half_rn(v11 - __half2float(h11)));
            } else if (g == 1) {
                *(uint32_t*)(g_kh + (size_t)row * DIMC + col) =
                    pack_h(__float2half_rn(v00), __float2half_rn(v01));
                *(uint32_t*)(g_kh + (size_t)(row + 8) * DIMC + col) =
                    pack_h(__float2half_rn(v10), __float2half_rn(v11));
            } else {
                size_t base0 = (size_t)(row >> 6) * 32768 + (size_t)col * 64 + (row & 63);
                g_vt[base0]      = __float2half_rn(v00);
                g_vt[base0 + 64] = __float2half_rn(v01);
                int row1 = row + 8;
                size_t base1 = (size_t)(row1 >> 6) * 32768 + (size_t)col * 64 + (row1 & 63);
                g_vt[base1]      = __float2half_rn(v10);
                g_vt[base1 + 64] = __float2half_rn(v11);
            }
        }
    }
}

// ---------------------------------------------------------------------------
// Proj GEMM: out = g_xh(fp16) @ Wp^T + bp. Single-pass fp16, all-cp.async.
// ---------------------------------------------------------------------------
#define SMEM_P  SMEM_G

__global__ __launch_bounds__(512, 1)
void gemm_proj(const float* __restrict__ bias, float* __restrict__ out) {
    extern __shared__ __half sm[];
    const uint32_t sb = (uint32_t)__cvta_generic_to_shared(sm);
    const __half* Wh = g_wblob + (size_t)3 * 262144;

    const int tid  = threadIdx.x;
    const int lane = tid & 31;
    const int wid  = tid >> 5;
    const int wm   = (wid >> 2) * 32;
    const int wn   = (wid & 3) * 64;
    const int n0   = blockIdx.x * 256;
    const int m0   = blockIdx.y * 128;

    const int arow  = tid >> 2;
    const int acolf = (tid & 3) * 8;
    const int brow  = tid >> 1;
    const int bcolf = (tid & 1) * 16;

    const int a_lrow = (lane & 15);
    const int a_lcol = (lane >> 4) * 8;
    const int b_lrow = ((lane >> 4) << 3) + (lane & 7);
    const int b_lcol = ((lane >> 3) & 1) * 8;

    float acc[2][8][4];
    #pragma unroll
    for (int i = 0; i < 2; i++)
        #pragma unroll
        for (int j = 0; j < 8; j++)
            #pragma unroll
            for (int r = 0; r < 4; r++) acc[i][j][r] = 0.f;

    auto stage = [&](int c, int st) {
        uint32_t dA = sb + (uint32_t)(st * STAGE_E + OFF_A + arow * SAK + acolf) * 2;
        cp16(dA, g_xh + (size_t)(m0 + arow) * DIMC + c * KC + acolf);
        uint32_t dB = sb + (uint32_t)(st * STAGE_E + OFF_B + brow * SAK + bcolf) * 2;
        const __half* srcB = Wh + (size_t)(n0 + brow) * DIMC + c * KC + bcolf;
        cp16(dB,      srcB);
        cp16(dB + 16, srcB + 8);
    };
    auto compute = [&](int st) {
        const uint32_t abase = sb + (uint32_t)(st * STAGE_E) * 2;
        #pragma unroll
        for (int ks = 0; ks < 2; ks++) {
            const int kc0 = ks * 16;
            uint32_t bf[8][2];
            uint32_t ah[2][4];
            #pragma unroll
            for (int i = 0; i < 2; i++) {
                ldsm_x4(ah[i], abase + (uint32_t)(OFF_A +
                    (wm + i * 16 + a_lrow) * SAK + kc0 + a_lcol) * 2);
            }
            #pragma unroll
            for (int gg = 0; gg < 4; gg++) {
                uint32_t r[4];
                ldsm_x4(r, abase + (uint32_t)(OFF_B +
                    (wn + gg * 16 + b_lrow) * SAK + kc0 + b_lcol) * 2);
                bf[2 * gg][0] = r[0]; bf[2 * gg][1] = r[1];
                bf[2 * gg + 1][0] = r[2]; bf[2 * gg + 1][1] = r[3];
            }
            #pragma unroll
            for (int i = 0; i < 2; i++)
                #pragma unroll
                for (int j = 0; j < 8; j++)
                    mma16816(acc[i][j], ah[i], bf[j]);
        }
    };

    stage(0, 0);
    asm volatile("cp.async.commit_group;" ::: "memory");

    for (int c = 0; c < 16; c++) {
        const int st  = c % 3;
        const int stn = (c + 1) % 3;
        if (c < 15) {
            stage(c + 1, stn);
            asm volatile("cp.async.commit_group;" ::: "memory");
            asm volatile("cp.async.wait_group 1;" ::: "memory");
        } else {
            asm volatile("cp.async.wait_group 0;" ::: "memory");
        }
        __syncthreads();
        compute(st);
    }

    #pragma unroll
    for (int j = 0; j < 8; j++) {
        int col = n0 + wn + j * 8 + (lane & 3) * 2;
        float b0 = __ldg(bias + col), b1 = __ldg(bias + col + 1);
        #pragma unroll
        for (int i = 0; i < 2; i++) {
            int row = m0 + wm + i * 16 + (lane >> 2);
            *(float2*)(out + (size_t)row * DIMC + col) =
                make_float2(acc[i][j][0] + b0, acc[i][j][1] + b1);
            *(float2*)(out + (size_t)(row + 8) * DIMC + col) =
                make_float2(acc[i][j][2] + b0, acc[i][j][3] + b1);
        }
    }
}

// ---------------------------------------------------------------------------
// Attention per (b,h): cp.async 4 fp16 tiles, S=QK^T, fp32 softmax,
// O=(Ph+Pl)V -> g_xh fp16.
// ---------------------------------------------------------------------------
#define SK2   72
#define TQH   0
#define TQL   4608
#define TKH   9216
#define TVT   13824
#define OFF_S 36864
#define OFF_M 54272
#define SMEM_A 54528

__global__ __launch_bounds__(128, 4)
void attn(const int* __restrict__ mask) {
    extern __shared__ __half sha[];
    __half* sQh = sha + TQH;
    __half* sQl = sha + TQL;
    float*  sS  = (float*)((char*)sha + OFF_S);
    int*  smask = (int*)((char*)sha + OFF_M);
    const uint32_t sb = (uint32_t)__cvta_generic_to_shared(sha);

    const int blk  = blockIdx.x;
    const int h    = blk & (HEADS - 1);
    const int b    = blk >> 3;
    const int tid  = threadIdx.x;
    const int lane = tid & 31;
    const int wid  = tid >> 5;
    const int wm   = wid * 16;

    if (tid < NTOK) smask[tid] = mask[b * NTOK + tid];

    {
        const __half* srcq = g_qh + (size_t)(b * 64) * DIMC + h * HD;
        const __half* srcl = g_ql + (size_t)(b * 64) * DIMC + h * HD;
        const __half* srck = g_kh + (size_t)(b * 64) * DIMC + h * HD;
        const __half* srcv = g_vt + (size_t)(b * 8 + h) * 4096;
        #pragma unroll
        for (int u = 0; u < 4; u++) {
            int seg = tid * 4 + u;
            int row = seg >> 3, s8 = (seg & 7) * 8;
            uint32_t dof = (uint32_t)(row * SK2 + s8) * 2;
            cp16(sb + (uint32_t)(TQH * 2) + dof, srcq + (size_t)row * DIMC + s8);
            cp16(sb + (uint32_t)(TQL * 2) + dof, srcl + (size_t)row * DIMC + s8);
            cp16(sb + (uint32_t)(TKH * 2) + dof, srck + (size_t)row * DIMC + s8);
            cp16(sb + (uint32_t)(TVT * 2) + dof, srcv + row * 64 + s8);
        }
        asm volatile("cp.async.commit_group;" ::: "memory");
        asm volatile("cp.async.wait_group 0;" ::: "memory");
    }
    __syncthreads();

    const int a_lrow = (lane & 15);
    const int a_lcol = (lane >> 4) * 8;
    const int b_lrow = ((lane >> 4) << 3) + (lane & 7);
    const int b_lcol = ((lane >> 3) & 1) * 8;

    {
        float acc[8][4];
        #pragma unroll
        for (int j = 0; j < 8; j++)
            #pragma unroll
            for (int r = 0; r < 4; r++) acc[j][r] = 0.f;
        #pragma unroll
        for (int ks = 0; ks < 4; ks++) {
            const int kc0 = ks * 16;
            uint32_t qh[4], ql[4], bf[8][2];
            uint32_t qaddr = sb + (uint32_t)(TQH + (wm + a_lrow) * SK2 + kc0 + a_lcol) * 2;
            ldsm_x4(qh, qaddr);
            ldsm_x4(ql, qaddr + (uint32_t)(TQL - TQH) * 2);
            #pragma unroll
            for (int gg = 0; gg < 4; gg++) {
                uint32_t r[4];
                ldsm_x4(r, sb + (uint32_t)(TKH + (gg * 16 + b_lrow) * SK2 + kc0 + b_lcol) * 2);
                bf[2 * gg][0] = r[0]; bf[2 * gg][1] = r[1];
                bf[2 * gg + 1][0] = r[2]; bf[2 * gg + 1][1] = r[3];
            }
            #pragma unroll
            for (int j = 0; j < 8; j++) mma16816(acc[j], qh, bf[j]);
            #pragma unroll
            for (int j = 0; j < 8; j++) mma16816(acc[j], ql, bf[j]);
        }
        #pragma unroll
        for (int j = 0; j < 8; j++) {
            int col = j * 8 + (lane & 3) * 2;
            int r0  = wm + (lane >> 2);
            sS[r0 * 68 + col]           = acc[j][0];
            sS[r0 * 68 + col + 1]       = acc[j][1];
            sS[(r0 + 8) * 68 + col]     = acc[j][2];
            sS[(r0 + 8) * 68 + col + 1] = acc[j][3];
        }
    }
    __syncthreads();

    {
        const int row = tid >> 1;
        const int p   = tid & 1;
        float v[32];
        float m = -1e30f;
        #pragma unroll
        for (int s = 0; s < 32; s++) {
            int j = p * 32 + s;
            float sv = sS[row * 68 + j];
            v[s] = (smask[j] != 0) ? sv : -10000.0f;
            m = fmaxf(m, v[s]);
        }
        m = fmaxf(m, __shfl_xor_sync(0xffffffffu, m, 1));
        float sum = 0.f;
        #pragma unroll
        for (int s = 0; s < 32; s++) { v[s] = __expf(v[s] - m); sum += v[s]; }
        sum += __shfl_xor_sync(0xffffffffu, sum, 1);
        float inv = 1.0f / sum;
        #pragma unroll
        for (int s = 0; s < 32; s++) {
            int j = p * 32 + s;
            float pv = v[s] * inv;
            __half ph = __float2half_rn(pv);
            sQh[row * SK2 + j] = ph;
            sQl[row * SK2 + j] = __float2half_rn(pv - __half2float(ph));
        }
    }
    __syncthreads();

    {
        float acc[8][4];
        #pragma unroll
        for (int j = 0; j < 8; j++)
            #pragma unroll
            for (int r = 0; r < 4; r++) acc[j][r] = 0.f;
        #pragma unroll
        for (int ks = 0; ks < 4; ks++) {
            const int kc0 = ks * 16;
            uint32_t ph[4], pl[4], bf[8][2];
            uint32_t paddr = sb + (uint32_t)(TQH + (wm + a_lrow) * SK2 + kc0 + a_lcol) * 2;
            ldsm_x4(ph, paddr);
            ldsm_x4(pl, paddr + (uint32_t)(TQL - TQH) * 2);
            #pragma unroll
            for (int gg = 0; gg < 4; gg++) {
                uint32_t r[4];
                ldsm_x4(r, sb + (uint32_t)(TVT + (gg * 16 + b_lrow) * SK2 + kc0 + b_lcol) * 2);
                bf[2 * gg][0] = r[0]; bf[2 * gg][1] = r[1];
                bf[2 * gg + 1][0] = r[2]; bf[2 * gg + 1][1] = r[3];
            }
            #pragma unroll
            for (int j = 0; j < 8; j++) mma16816(acc[j], ph, bf[j]);
            #pragma unroll
            for (int j = 0; j < 8; j++) mma16816(acc[j], pl, bf[j]);
        }
        #pragma unroll
        for (int j = 0; j < 8; j++) {
            int col = h * HD + j * 8 + (lane & 3) * 2;
            int r0  = wm + (lane >> 2);
            *(uint32_t*)(g_xh + (size_t)(b * 64 + r0) * DIMC + col) =
                pack_h(__float2half_rn(acc[j][0]), __float2half_rn(acc[j][1]));
            *(uint32_t*)(g_xh + (size_t)(b * 64 + r0 + 8) * DIMC + col) =
                pack_h(__float2half_rn(acc[j][2]), __float2half_rn(acc[j][3]));
        }
    }
}

// ---------------------------------------------------------------------------
extern "C" void kernel_launch(void* const* d_in, const int* in_sizes, int n_in,
                              void* d_out, int out_size) {
    const float* q    = (const float*)d_in[0];
    const float* k    = (const float*)d_in[1];
    const float* v    = (const float*)d_in[2];
    const int*   mask = (const int*)  d_in[3];
    const float* Wq   = (const float*)d_in[4];
    const float* bq   = (const float*)d_in[5];
    const float* Wk   = (const float*)d_in[6];
    const float* bk   = (const float*)d_in[7];
    const float* Wv   = (const float*)d_in[8];
    const float* bv   = (const float*)d_in[9];
    const float* Wp   = (const float*)d_in[10];
    const float* bp   = (const float*)d_in[11];
    float* out = (float*)d_out;

    cudaFuncSetAttribute(gemm_qkv,  cudaFuncAttributeMaxDynamicSharedMemorySize, SMEM_G);
    cudaFuncSetAttribute(gemm_proj, cudaFuncAttributeMaxDynamicSharedMemorySize, SMEM_P);
    cudaFuncSetAttribute(attn,      cudaFuncAttributeMaxDynamicSharedMemorySize, SMEM_A);

    conv_w<<<4096, 256>>>(Wq, Wk, Wv, Wp);

    dim3 gqkv(DIMC / 256, MROWS / 128, 3);
    gemm_qkv<<<gqkv, 512, SMEM_G>>>(q, k, v, bq, bk, bv);

    attn<<<BATCH * HEADS, 128, SMEM_A>>>(mask);

    dim3 gp(DIMC / 256, MROWS / 128);
    gemm_proj<<<gp, 512, SMEM_P>>>(bp, out);
}

// round 15
// speedup vs baseline: 1.5212x; 1.0013x over previous
#include <cuda_runtime.h>
#include <cuda_fp16.h>
#include <cstdint>

#define DIMC   512
#define HEADS  8
#define HD     64
#define NTOK   64
#define BATCH  2048
#define MROWS  (BATCH * NTOK)     // 131072
#define SCALE_Q 0.125f

// ---------------- device scratch ----------------
__device__ __half g_qh[(size_t)MROWS * DIMC];   // Q hi (scale folded)
__device__ __half g_ql[(size_t)MROWS * DIMC];   // Q lo
__device__ __half g_kh[(size_t)MROWS * DIMC];   // K hi
__device__ __half g_vt[(size_t)MROWS * DIMC];   // V hi, transposed [b][h][d][token]
__device__ __half g_xh[(size_t)MROWS * DIMC];   // attn out (fp16)
__device__ __align__(128) __half g_wblob[(size_t)4 * 512 * 512];

// ---------------------------------------------------------------------------
// Kernel 0: weights -> fp16 blobs. Wq pre-scaled by SCALE_Q (exact pow2).
// ---------------------------------------------------------------------------
__global__ void conv_w(const float* __restrict__ Wq, const float* __restrict__ Wk,
                       const float* __restrict__ Wv, const float* __restrict__ Wp) {
    int idx = blockIdx.x * 256 + threadIdx.x;
    int g   = idx >> 18;
    int rem = idx & 262143;
    const float* W = (g == 0) ? Wq : (g == 1) ? Wk : (g == 2) ? Wv : Wp;
    float w = W[rem] * ((g == 0) ? SCALE_Q : 1.0f);
    g_wblob[(size_t)g * 262144 + rem] = __float2half_rn(w);
}

// ---------------------------------------------------------------------------
// common MMA helpers
// ---------------------------------------------------------------------------
__device__ __forceinline__ void mma16816(float* d, const uint32_t* a, const uint32_t* b) {
    asm volatile(
        "mma.sync.aligned.m16n8k16.row.col.f32.f16.f16.f32 "
        "{%0,%1,%2,%3}, {%4,%5,%6,%7}, {%8,%9}, {%0,%1,%2,%3};"
        : "+f"(d[0]), "+f"(d[1]), "+f"(d[2]), "+f"(d[3])
        : "r"(a[0]), "r"(a[1]), "r"(a[2]), "r"(a[3]), "r"(b[0]), "r"(b[1]));
}
__device__ __forceinline__ void ldsm_x4(uint32_t* r, uint32_t addr) {
    asm volatile("ldmatrix.sync.aligned.m8n8.x4.shared.b16 {%0,%1,%2,%3}, [%4];"
        : "=r"(r[0]), "=r"(r[1]), "=r"(r[2]), "=r"(r[3]) : "r"(addr));
}
__device__ __forceinline__ void cp16(uint32_t dst, const void* src) {
    asm volatile("cp.async.cg.shared.global [%0], [%1], 16;" :: "r"(dst), "l"(src));
}
__device__ __forceinline__ uint32_t pack_h(__half a, __half b) {
    return (uint32_t)__half_as_ushort(a) | ((uint32_t)__half_as_ushort(b) << 16);
}

// ---------------------------------------------------------------------------
// Fused QKV GEMM (grid.z = g): SINGLE-PASS fp16 (inputs quantized to fp16 at
// staging). Epilogues: 0=Q->hi/lo fp16 (from fp32 acc), 1=K->fp16, 2=V->fp16^T.
// ---------------------------------------------------------------------------
#define KC      32
#define SAK     40
#define OFF_A   0
#define OFF_B   (128 * SAK)
#define STAGE_E (128 * SAK + 256 * SAK)           // 15360 halves
#define SMEM_G  (3 * STAGE_E * 2)                  // 92160 bytes

__global__ __launch_bounds__(512, 1)
void gemm_qkv(const float* __restrict__ qin, const float* __restrict__ kin,
              const float* __restrict__ vin,
              const float* __restrict__ bq, const float* __restrict__ bk,
              const float* __restrict__ bv) {
    extern __shared__ __half sm[];
    const uint32_t sb = (uint32_t)__cvta_generic_to_shared(sm);

    const int g = blockIdx.z;
    const float* A    = (g == 0) ? qin : (g == 1) ? kin : vin;
    const float* bias = (g == 0) ? bq  : (g == 1) ? bk  : bv;
    const __half* Wh  = g_wblob + (size_t)g * 262144;

    const int tid  = threadIdx.x;
    const int lane = tid & 31;
    const int wid  = tid >> 5;
    const int wm   = (wid >> 2) * 32;
    const int wn   = (wid & 3) * 64;
    const int n0   = blockIdx.x * 256;
    const int m0   = blockIdx.y * 128;

    const int arow  = tid >> 2;
    const int acolf = (tid & 3) * 8;
    const int brow  = tid >> 1;
    const int bcolf = (tid & 1) * 16;

    const int a_lrow = (lane & 15);
    const int a_lcol = (lane >> 4) * 8;
    const int b_lrow = ((lane >> 4) << 3) + (lane & 7);
    const int b_lcol = ((lane >> 3) & 1) * 8;

    float acc[2][8][4];
    #pragma unroll
    for (int i = 0; i < 2; i++)
        #pragma unroll
        for (int j = 0; j < 8; j++)
            #pragma unroll
            for (int r = 0; r < 4; r++) acc[i][j][r] = 0.f;

    float4 rA[2];

    auto stageB = [&](int c, int st) {
        uint32_t dst = sb + (uint32_t)(st * STAGE_E + OFF_B + brow * SAK + bcolf) * 2;
        const __half* src = Wh + (size_t)(n0 + brow) * DIMC + c * KC + bcolf;
        cp16(dst,      src);
        cp16(dst + 16, src + 8);
    };
    auto ldgA = [&](int c) {
        const float* src = A + (size_t)(m0 + arow) * DIMC + c * KC + acolf;
        rA[0] = __ldg((const float4*)src);
        rA[1] = __ldg((const float4*)(src + 4));
    };
    auto stsA = [&](int st) {
        __half* sA = sm + st * STAGE_E + OFF_A + arow * SAK + acolf;
        #pragma unroll
        for (int u = 0; u < 2; u++) {
            float4 f = rA[u];
            *(uint2*)(sA + u * 4) = make_uint2(
                pack_h(__float2half_rn(f.x), __float2half_rn(f.y)),
                pack_h(__float2half_rn(f.z), __float2half_rn(f.w)));
        }
    };
    auto compute = [&](int st) {
        const uint32_t abase = sb + (uint32_t)(st * STAGE_E) * 2;
        #pragma unroll
        for (int ks = 0; ks < 2; ks++) {
            const int kc0 = ks * 16;
            uint32_t bf[8][2];
            uint32_t ah[2][4];
            #pragma unroll
            for (int i = 0; i < 2; i++) {
                ldsm_x4(ah[i], abase + (uint32_t)(OFF_A +
                    (wm + i * 16 + a_lrow) * SAK + kc0 + a_lcol) * 2);
            }
            #pragma unroll
            for (int gg = 0; gg < 4; gg++) {
                uint32_t r[4];
                ldsm_x4(r, abase + (uint32_t)(OFF_B +
                    (wn + gg * 16 + b_lrow) * SAK + kc0 + b_lcol) * 2);
                bf[2 * gg][0] = r[0]; bf[2 * gg][1] = r[1];
                bf[2 * gg + 1][0] = r[2]; bf[2 * gg + 1][1] = r[3];
            }
            #pragma unroll
            for (int i = 0; i < 2; i++)
                #pragma unroll
                for (int j = 0; j < 8; j++)
                    mma16816(acc[i][j], ah[i], bf[j]);
        }
    };

    stageB(0, 0);
    asm volatile("cp.async.commit_group;" ::: "memory");
    ldgA(0);
    stsA(0);

    for (int c = 0; c < 16; c++) {
        const int st  = c % 3;
        const int stn = (c + 1) % 3;
        if (c < 15) {
            ldgA(c + 1);
            stageB(c + 1, stn);
            asm volatile("cp.async.commit_group;" ::: "memory");
            asm volatile("cp.async.wait_group 1;" ::: "memory");
        } else {
            asm volatile("cp.async.wait_group 0;" ::: "memory");
        }
        __syncthreads();
        compute(st);
        if (c < 15) stsA(stn);
    }

    // ---- epilogue per g ----
    #pragma unroll
    for (int j = 0; j < 8; j++) {
        int col = n0 + wn + j * 8 + (lane & 3) * 2;
        float bscale = (g == 0) ? SCALE_Q : 1.0f;
        float b0 = __ldg(bias + col) * bscale, b1 = __ldg(bias + col + 1) * bscale;
        #pragma unroll
        for (int i = 0; i < 2; i++) {
            int row = m0 + wm + i * 16 + (lane >> 2);
            float v00 = acc[i][j][0] + b0, v01 = acc[i][j][1] + b1;
            float v10 = acc[i][j][2] + b0, v11 = acc[i][j][3] + b1;
            if (g == 0) {
                __half h00 = __float2half_rn(v00), h01 = __float2half_rn(v01);
                __half h10 = __float2half_rn(v10), h11 = __float2half_rn(v11);
                *(uint32_t*)(g_qh + (size_t)row * DIMC + col)       = pack_h(h00, h01);
                *(uint32_t*)(g_qh + (size_t)(row + 8) * DIMC + col) = pack_h(h10, h11);
                *(uint32_t*)(g_ql + (size_t)row * DIMC + col) =
                    pack_h(__float2half_rn(v00 - __half2float(h00)),
                           __float2half_rn(v01 - __half2float(h01)));
                *(uint32_t*)(g_ql + (size_t)(row + 8) * DIMC + col) =
                    pack_h(__float2half_rn(v10 - __half2float(h10)),
                           __float2half_rn(v11 - __half2float(h11)));
            } else if (g == 1) {
                *(uint32_t*)(g_kh + (size_t)row * DIMC + col) =
                    pack_h(__float2half_rn(v00), __float2half_rn(v01));
                *(uint32_t*)(g_kh + (size_t)(row + 8) * DIMC + col) =
                    pack_h(__float2half_rn(v10), __float2half_rn(v11));
            } else {
                size_t base0 = (size_t)(row >> 6) * 32768 + (size_t)col * 64 + (row & 63);
                g_vt[base0]      = __float2half_rn(v00);
                g_vt[base0 + 64] = __float2half_rn(v01);
                int row1 = row + 8;
                size_t base1 = (size_t)(row1 >> 6) * 32768 + (size_t)col * 64 + (row1 & 63);
                g_vt[base1]      = __float2half_rn(v10);
                g_vt[base1 + 64] = __float2half_rn(v11);
            }
        }
    }
}

// ---------------------------------------------------------------------------
// Proj GEMM: out = g_xh(fp16) @ Wp^T + bp. Single-pass fp16, all-cp.async.
// ---------------------------------------------------------------------------
#define SMEM_P  SMEM_G

__global__ __launch_bounds__(512, 1)
void gemm_proj(const float* __restrict__ bias, float* __restrict__ out) {
    extern __shared__ __half sm[];
    const uint32_t sb = (uint32_t)__cvta_generic_to_shared(sm);
    const __half* Wh = g_wblob + (size_t)3 * 262144;

    const int tid  = threadIdx.x;
    const int lane = tid & 31;
    const int wid  = tid >> 5;
    const int wm   = (wid >> 2) * 32;
    const int wn   = (wid & 3) * 64;
    const int n0   = blockIdx.x * 256;
    const int m0   = blockIdx.y * 128;

    const int arow  = tid >> 2;
    const int acolf = (tid & 3) * 8;
    const int brow  = tid >> 1;
    const int bcolf = (tid & 1) * 16;

    const int a_lrow = (lane & 15);
    const int a_lcol = (lane >> 4) * 8;
    const int b_lrow = ((lane >> 4) << 3) + (lane & 7);
    const int b_lcol = ((lane >> 3) & 1) * 8;

    float acc[2][8][4];
    #pragma unroll
    for (int i = 0; i < 2; i++)
        #pragma unroll
        for (int j = 0; j < 8; j++)
            #pragma unroll
            for (int r = 0; r < 4; r++) acc[i][j][r] = 0.f;

    auto stage = [&](int c, int st) {
        uint32_t dA = sb + (uint32_t)(st * STAGE_E + OFF_A + arow * SAK + acolf) * 2;
        cp16(dA, g_xh + (size_t)(m0 + arow) * DIMC + c * KC + acolf);
        uint32_t dB = sb + (uint32_t)(st * STAGE_E + OFF_B + brow * SAK + bcolf) * 2;
        const __half* srcB = Wh + (size_t)(n0 + brow) * DIMC + c * KC + bcolf;
        cp16(dB,      srcB);
        cp16(dB + 16, srcB + 8);
    };
    auto compute = [&](int st) {
        const uint32_t abase = sb + (uint32_t)(st * STAGE_E) * 2;
        #pragma unroll
        for (int ks = 0; ks < 2; ks++) {
            const int kc0 = ks * 16;
            uint32_t bf[8][2];
            uint32_t ah[2][4];
            #pragma unroll
            for (int i = 0; i < 2; i++) {
                ldsm_x4(ah[i], abase + (uint32_t)(OFF_A +
                    (wm + i * 16 + a_lrow) * SAK + kc0 + a_lcol) * 2);
            }
            #pragma unroll
            for (int gg = 0; gg < 4; gg++) {
                uint32_t r[4];
                ldsm_x4(r, abase + (uint32_t)(OFF_B +
                    (wn + gg * 16 + b_lrow) * SAK + kc0 + b_lcol) * 2);
                bf[2 * gg][0] = r[0]; bf[2 * gg][1] = r[1];
                bf[2 * gg + 1][0] = r[2]; bf[2 * gg + 1][1] = r[3];
            }
            #pragma unroll
            for (int i = 0; i < 2; i++)
                #pragma unroll
                for (int j = 0; j < 8; j++)
                    mma16816(acc[i][j], ah[i], bf[j]);
        }
    };

    stage(0, 0);
    asm volatile("cp.async.commit_group;" ::: "memory");

    for (int c = 0; c < 16; c++) {
        const int st  = c % 3;
        const int stn = (c + 1) % 3;
        if (c < 15) {
            stage(c + 1, stn);
            asm volatile("cp.async.commit_group;" ::: "memory");
            asm volatile("cp.async.wait_group 1;" ::: "memory");
        } else {
            asm volatile("cp.async.wait_group 0;" ::: "memory");
        }
        __syncthreads();
        compute(st);
    }

    #pragma unroll
    for (int j = 0; j < 8; j++) {
        int col = n0 + wn + j * 8 + (lane & 3) * 2;
        float b0 = __ldg(bias + col), b1 = __ldg(bias + col + 1);
        #pragma unroll
        for (int i = 0; i < 2; i++) {
            int row = m0 + wm + i * 16 + (lane >> 2);
            *(float2*)(out + (size_t)row * DIMC + col) =
                make_float2(acc[i][j][0] + b0, acc[i][j][1] + b1);
            *(float2*)(out + (size_t)(row + 8) * DIMC + col) =
                make_float2(acc[i][j][2] + b0, acc[i][j][3] + b1);
        }
    }
}

// ---------------------------------------------------------------------------
// Attention per (b,h): cp.async 4 fp16 tiles, S=QK^T, fp32 softmax,
// O=(Ph+Pl)V -> g_xh fp16.
// ---------------------------------------------------------------------------
#define SK2   72
#define TQH   0
#define TQL   4608
#define TKH   9216
#define TVT   13824
#define OFF_S 36864
#define OFF_M 54272
#define SMEM_A 54528

__global__ __launch_bounds__(128, 4)
void attn(const int* __restrict__ mask) {
    extern __shared__ __half sha[];
    __half* sQh = sha + TQH;
    __half* sQl = sha + TQL;
    float*  sS  = (float*)((char*)sha + OFF_S);
    int*  smask = (int*)((char*)sha + OFF_M);
    const uint32_t sb = (uint32_t)__cvta_generic_to_shared(sha);

    const int blk  = blockIdx.x;
    const int h    = blk & (HEADS - 1);
    const int b    = blk >> 3;
    const int tid  = threadIdx.x;
    const int lane = tid & 31;
    const int wid  = tid >> 5;
    const int wm   = wid * 16;

    if (tid < NTOK) smask[tid] = mask[b * NTOK + tid];

    {
        const __half* srcq = g_qh + (size_t)(b * 64) * DIMC + h * HD;
        const __half* srcl = g_ql + (size_t)(b * 64) * DIMC + h * HD;
        const __half* srck = g_kh + (size_t)(b * 64) * DIMC + h * HD;
        const __half* srcv = g_vt + (size_t)(b * 8 + h) * 4096;
        #pragma unroll
        for (int u = 0; u < 4; u++) {
            int seg = tid * 4 + u;
            int row = seg >> 3, s8 = (seg & 7) * 8;
            uint32_t dof = (uint32_t)(row * SK2 + s8) * 2;
            cp16(sb + (uint32_t)(TQH * 2) + dof, srcq + (size_t)row * DIMC + s8);
            cp16(sb + (uint32_t)(TQL * 2) + dof, srcl + (size_t)row * DIMC + s8);
            cp16(sb + (uint32_t)(TKH * 2) + dof, srck + (size_t)row * DIMC + s8);
            cp16(sb + (uint32_t)(TVT * 2) + dof, srcv + row * 64 + s8);
        }
        asm volatile("cp.async.commit_group;" ::: "memory");
        asm volatile("cp.async.wait_group 0;" ::: "memory");
    }
    __syncthreads();

    const int a_lrow = (lane & 15);
    const int a_lcol = (lane >> 4) * 8;
    const int b_lrow = ((lane >> 4) << 3) + (lane & 7);
    const int b_lcol = ((lane >> 3) & 1) * 8;

    {
        float acc[8][4];
        #pragma unroll
        for (int j = 0; j < 8; j++)
            #pragma unroll
            for (int r = 0; r < 4; r++) acc[j][r] = 0.f;
        #pragma unroll
        for (int ks = 0; ks < 4; ks++) {
            const int kc0 = ks * 16;
            uint32_t qh[4], ql[4], bf[8][2];
            uint32_t qaddr = sb + (uint32_t)(TQH + (wm + a_lrow) * SK2 + kc0 + a_lcol) * 2;
            ldsm_x4(qh, qaddr);
            ldsm_x4(ql, qaddr + (uint32_t)(TQL - TQH) * 2);
            #pragma unroll
            for (int gg = 0; gg < 4; gg++) {
                uint32_t r[4];
                ldsm_x4(r, sb + (uint32_t)(TKH + (gg * 16 + b_lrow) * SK2 + kc0 + b_lcol) * 2);
                bf[2 * gg][0] = r[0]; bf[2 * gg][1] = r[1];
                bf[2 * gg + 1][0] = r[2]; bf[2 * gg + 1][1] = r[3];
            }
            #pragma unroll
            for (int j = 0; j < 8; j++) mma16816(acc[j], qh, bf[j]);
            #pragma unroll
            for (int j = 0; j < 8; j++) mma16816(acc[j], ql, bf[j]);
        }
        #pragma unroll
        for (int j = 0; j < 8; j++) {
            int col = j * 8 + (lane & 3) * 2;
            int r0  = wm + (lane >> 2);
            sS[r0 * 68 + col]           = acc[j][0];
            sS[r0 * 68 + col + 1]       = acc[j][1];
            sS[(r0 + 8) * 68 + col]     = acc[j][2];
            sS[(r0 + 8) * 68 + col + 1] = acc[j][3];
        }
    }
    __syncthreads();

    {
        const int row = tid >> 1;
        const int p   = tid & 1;
        float v[32];
        float m = -1e30f;
        #pragma unroll
        for (int s = 0; s < 32; s++) {
            int j = p * 32 + s;
            float sv = sS[row * 68 + j];
            v[s] = (smask[j] != 0) ? sv : -10000.0f;
            m = fmaxf(m, v[s]);
        }
        m = fmaxf(m, __shfl_xor_sync(0xffffffffu, m, 1));
        float sum = 0.f;
        #pragma unroll
        for (int s = 0; s < 32; s++) { v[s] = __expf(v[s] - m); sum += v[s]; }
        sum += __shfl_xor_sync(0xffffffffu, sum, 1);
        float inv = 1.0f / sum;
        #pragma unroll
        for (int s = 0; s < 32; s++) {
            int j = p * 32 + s;
            float pv = v[s] * inv;
            __half ph = __float2half_rn(pv);
            sQh[row * SK2 + j] = ph;
            sQl[row * SK2 + j] = __float2half_rn(pv - __half2float(ph));
        }
    }
    __syncthreads();

    {
        float acc[8][4];
        #pragma unroll
        for (int j = 0; j < 8; j++)
            #pragma unroll
            for (int r = 0; r < 4; r++) acc[j][r] = 0.f;
        #pragma unroll
        for (int ks = 0; ks < 4; ks++) {
            const int kc0 = ks * 16;
            uint32_t ph[4], pl[4], bf[8][2];
            uint32_t paddr = sb + (uint32_t)(TQH + (wm + a_lrow) * SK2 + kc0 + a_lcol) * 2;
            ldsm_x4(ph, paddr);
            ldsm_x4(pl, paddr + (uint32_t)(TQL - TQH) * 2);
            #pragma unroll
            for (int gg = 0; gg < 4; gg++) {
                uint32_t r[4];
                ldsm_x4(r, sb + (uint32_t)(TVT + (gg * 16 + b_lrow) * SK2 + kc0 + b_lcol) * 2);
                bf[2 * gg][0] = r[0]; bf[2 * gg][1] = r[1];
                bf[2 * gg + 1][0] = r[2]; bf[2 * gg + 1][1] = r[3];
            }
            #pragma unroll
            for (int j = 0; j < 8; j++) mma16816(acc[j], ph, bf[j]);
            #pragma unroll
            for (int j = 0; j < 8; j++) mma16816(acc[j], pl, bf[j]);
        }
        #pragma unroll
        for (int j = 0; j < 8; j++) {
            int col = h * HD + j * 8 + (lane & 3) * 2;
            int r0  = wm + (lane >> 2);
            *(uint32_t*)(g_xh + (size_t)(b * 64 + r0) * DIMC + col) =
                pack_h(__float2half_rn(acc[j][0]), __float2half_rn(acc[j][1]));
            *(uint32_t*)(g_xh + (size_t)(b * 64 + r0 + 8) * DIMC + col) =
                pack_h(__float2half_rn(acc[j][2]), __float2half_rn(acc[j][3]));
        }
    }
}

// ---------------------------------------------------------------------------
extern "C" void kernel_launch(void* const* d_in, const int* in_sizes, int n_in,
                              void* d_out, int out_size) {
    const float* q    = (const float*)d_in[0];
    const float* k    = (const float*)d_in[1];
    const float* v    = (const float*)d_in[2];
    const int*   mask = (const int*)  d_in[3];
    const float* Wq   = (const float*)d_in[4];
    const float* bq   = (const float*)d_in[5];
    const float* Wk   = (const float*)d_in[6];
    const float* bk   = (const float*)d_in[7];
    const float* Wv   = (const float*)d_in[8];
    const float* bv   = (const float*)d_in[9];
    const float* Wp   = (const float*)d_in[10];
    const float* bp   = (const float*)d_in[11];
    float* out = (float*)d_out;

    cudaFuncSetAttribute(gemm_qkv,  cudaFuncAttributeMaxDynamicSharedMemorySize, SMEM_G);
    cudaFuncSetAttribute(gemm_proj, cudaFuncAttributeMaxDynamicSharedMemorySize, SMEM_P);
    cudaFuncSetAttribute(attn,      cudaFuncAttributeMaxDynamicSharedMemorySize, SMEM_A);

    conv_w<<<4096, 256>>>(Wq, Wk, Wv, Wp);

    dim3 gqkv(DIMC / 256, MROWS / 128, 3);
    gemm_qkv<<<gqkv, 512, SMEM_G>>>(q, k, v, bq, bk, bv);

    attn<<<BATCH * HEADS, 128, SMEM_A>>>(mask);

    dim3 gp(DIMC / 256, MROWS / 128);
    gemm_proj<<<gp, 512, SMEM_P>>>(bp, out);
}

// round 16
// speedup vs baseline: 1.5313x; 1.0067x over previous
#include <cuda_runtime.h>
#include <cuda_fp16.h>
#include <cstdint>

#define DIMC   512
#define HEADS  8
#define HD     64
#define NTOK   64
#define BATCH  2048
#define MROWS  (BATCH * NTOK)     // 131072
#define SCALE_Q 0.125f

// ---------------- device scratch ----------------
__device__ __half g_qh[(size_t)MROWS * DIMC];   // Q hi (scale folded)
__device__ __half g_ql[(size_t)MROWS * DIMC];   // Q lo
__device__ __half g_kh[(size_t)MROWS * DIMC];   // K hi
__device__ __half g_vt[(size_t)MROWS * DIMC];   // V hi, transposed [b][h][d][token]
__device__ __half g_xh[(size_t)MROWS * DIMC];   // attn out (fp16)
__device__ __align__(128) __half g_wblob[(size_t)4 * 512 * 512];

// ---------------------------------------------------------------------------
// Kernel 0: weights -> fp16 blobs. Wq pre-scaled by SCALE_Q (exact pow2).
// ---------------------------------------------------------------------------
__global__ void conv_w(const float* __restrict__ Wq, const float* __restrict__ Wk,
                       const float* __restrict__ Wv, const float* __restrict__ Wp) {
    int idx = blockIdx.x * 256 + threadIdx.x;
    int g   = idx >> 18;
    int rem = idx & 262143;
    const float* W = (g == 0) ? Wq : (g == 1) ? Wk : (g == 2) ? Wv : Wp;
    float w = W[rem] * ((g == 0) ? SCALE_Q : 1.0f);
    g_wblob[(size_t)g * 262144 + rem] = __float2half_rn(w);
}

// ---------------------------------------------------------------------------
// common MMA helpers
// ---------------------------------------------------------------------------
__device__ __forceinline__ void mma16816(float* d, const uint32_t* a, const uint32_t* b) {
    asm volatile(
        "mma.sync.aligned.m16n8k16.row.col.f32.f16.f16.f32 "
        "{%0,%1,%2,%3}, {%4,%5,%6,%7}, {%8,%9}, {%0,%1,%2,%3};"
        : "+f"(d[0]), "+f"(d[1]), "+f"(d[2]), "+f"(d[3])
        : "r"(a[0]), "r"(a[1]), "r"(a[2]), "r"(a[3]), "r"(b[0]), "r"(b[1]));
}
__device__ __forceinline__ void ldsm_x4(uint32_t* r, uint32_t addr) {
    asm volatile("ldmatrix.sync.aligned.m8n8.x4.shared.b16 {%0,%1,%2,%3}, [%4];"
        : "=r"(r[0]), "=r"(r[1]), "=r"(r[2]), "=r"(r[3]) : "r"(addr));
}
__device__ __forceinline__ void cp16(uint32_t dst, const void* src) {
    asm volatile("cp.async.cg.shared.global [%0], [%1], 16;" :: "r"(dst), "l"(src));
}
__device__ __forceinline__ uint32_t pack_h(__half a, __half b) {
    return (uint32_t)__half_as_ushort(a) | ((uint32_t)__half_as_ushort(b) << 16);
}

// ---------------------------------------------------------------------------
// Fused QKV GEMM (grid.z = g): single-pass fp16. Epilogues:
// 0=Q->hi/lo fp16, 1=K->fp16, 2=V->fp16 transposed.
// ---------------------------------------------------------------------------
#define KC      32
#define SAK     40
#define OFF_A   0
#define OFF_B   (128 * SAK)
#define STAGE_E (128 * SAK + 256 * SAK)
#define SMEM_G  (3 * STAGE_E * 2)

__global__ __launch_bounds__(512, 1)
void gemm_qkv(const float* __restrict__ qin, const float* __restrict__ kin,
              const float* __restrict__ vin,
              const float* __restrict__ bq, const float* __restrict__ bk,
              const float* __restrict__ bv) {
    extern __shared__ __half sm[];
    const uint32_t sb = (uint32_t)__cvta_generic_to_shared(sm);

    const int g = blockIdx.z;
    const float* A    = (g == 0) ? qin : (g == 1) ? kin : vin;
    const float* bias = (g == 0) ? bq  : (g == 1) ? bk  : bv;
    const __half* Wh  = g_wblob + (size_t)g * 262144;

    const int tid  = threadIdx.x;
    const int lane = tid & 31;
    const int wid  = tid >> 5;
    const int wm   = (wid >> 2) * 32;
    const int wn   = (wid & 3) * 64;
    const int n0   = blockIdx.x * 256;
    const int m0   = blockIdx.y * 128;

    const int arow  = tid >> 2;
    const int acolf = (tid & 3) * 8;
    const int brow  = tid >> 1;
    const int bcolf = (tid & 1) * 16;

    const int a_lrow = (lane & 15);
    const int a_lcol = (lane >> 4) * 8;
    const int b_lrow = ((lane >> 4) << 3) + (lane & 7);
    const int b_lcol = ((lane >> 3) & 1) * 8;

    float acc[2][8][4];
    #pragma unroll
    for (int i = 0; i < 2; i++)
        #pragma unroll
        for (int j = 0; j < 8; j++)
            #pragma unroll
            for (int r = 0; r < 4; r++) acc[i][j][r] = 0.f;

    float4 rA[2];

    auto stageB = [&](int c, int st) {
        uint32_t dst = sb + (uint32_t)(st * STAGE_E + OFF_B + brow * SAK + bcolf) * 2;
        const __half* src = Wh + (size_t)(n0 + brow) * DIMC + c * KC + bcolf;
        cp16(dst,      src);
        cp16(dst + 16, src + 8);
    };
    auto ldgA = [&](int c) {
        const float* src = A + (size_t)(m0 + arow) * DIMC + c * KC + acolf;
        rA[0] = __ldg((const float4*)src);
        rA[1] = __ldg((const float4*)(src + 4));
    };
    auto stsA = [&](int st) {
        __half* sA = sm + st * STAGE_E + OFF_A + arow * SAK + acolf;
        #pragma unroll
        for (int u = 0; u < 2; u++) {
            float4 f = rA[u];
            *(uint2*)(sA + u * 4) = make_uint2(
                pack_h(__float2half_rn(f.x), __float2half_rn(f.y)),
                pack_h(__float2half_rn(f.z), __float2half_rn(f.w)));
        }
    };
    auto compute = [&](int st) {
        const uint32_t abase = sb + (uint32_t)(st * STAGE_E) * 2;
        #pragma unroll
        for (int ks = 0; ks < 2; ks++) {
            const int kc0 = ks * 16;
            uint32_t bf[8][2];
            uint32_t ah[2][4];
            #pragma unroll
            for (int i = 0; i < 2; i++) {
                ldsm_x4(ah[i], abase + (uint32_t)(OFF_A +
                    (wm + i * 16 + a_lrow) * SAK + kc0 + a_lcol) * 2);
            }
            #pragma unroll
            for (int gg = 0; gg < 4; gg++) {
                uint32_t r[4];
                ldsm_x4(r, abase + (uint32_t)(OFF_B +
                    (wn + gg * 16 + b_lrow) * SAK + kc0 + b_lcol) * 2);
                bf[2 * gg][0] = r[0]; bf[2 * gg][1] = r[1];
                bf[2 * gg + 1][0] = r[2]; bf[2 * gg + 1][1] = r[3];
            }
            #pragma unroll
            for (int i = 0; i < 2; i++)
                #pragma unroll
                for (int j = 0; j < 8; j++)
                    mma16816(acc[i][j], ah[i], bf[j]);
        }
    };

    stageB(0, 0);
    asm volatile("cp.async.commit_group;" ::: "memory");
    ldgA(0);
    stsA(0);

    for (int c = 0; c < 16; c++) {
        const int st  = c % 3;
        const int stn = (c + 1) % 3;
        if (c < 15) {
            ldgA(c + 1);
            stageB(c + 1, stn);
            asm volatile("cp.async.commit_group;" ::: "memory");
            asm volatile("cp.async.wait_group 1;" ::: "memory");
        } else {
            asm volatile("cp.async.wait_group 0;" ::: "memory");
        }
        __syncthreads();
        compute(st);
        if (c < 15) stsA(stn);
    }

    #pragma unroll
    for (int j = 0; j < 8; j++) {
        int col = n0 + wn + j * 8 + (lane & 3) * 2;
        float bscale = (g == 0) ? SCALE_Q : 1.0f;
        float b0 = __ldg(bias + col) * bscale, b1 = __ldg(bias + col + 1) * bscale;
        #pragma unroll
        for (int i = 0; i < 2; i++) {
            int row = m0 + wm + i * 16 + (lane >> 2);
            float v00 = acc[i][j][0] + b0, v01 = acc[i][j][1] + b1;
            float v10 = acc[i][j][2] + b0, v11 = acc[i][j][3] + b1;
            if (g == 0) {
                __half h00 = __float2half_rn(v00), h01 = __float2half_rn(v01);
                __half h10 = __float2half_rn(v10), h11 = __float2half_rn(v11);
                *(uint32_t*)(g_qh + (size_t)row * DIMC + col)       = pack_h(h00, h01);
                *(uint32_t*)(g_qh + (size_t)(row + 8) * DIMC + col) = pack_h(h10, h11);
                *(uint32_t*)(g_ql + (size_t)row * DIMC + col) =
                    pack_h(__float2half_rn(v00 - __half2float(h00)),
                           __float2half_rn(v01 - __half2float(h01)));
                *(uint32_t*)(g_ql + (size_t)(row + 8) * DIMC + col) =
                    pack_h(__float2half_rn(v10 - __half2float(h10)),
                           __float2half_rn(v11 - __half2float(h11)));
            } else if (g == 1) {
                *(uint32_t*)(g_kh + (size_t)row * DIMC + col) =
                    pack_h(__float2half_rn(v00), __float2half_rn(v01));
                *(uint32_t*)(g_kh + (size_t)(row + 8) * DIMC + col) =
                    pack_h(__float2half_rn(v10), __float2half_rn(v11));
            } else {
                size_t base0 = (size_t)(row >> 6) * 32768 + (size_t)col * 64 + (row & 63);
                g_vt[base0]      = __float2half_rn(v00);
                g_vt[base0 + 64] = __float2half_rn(v01);
                int row1 = row + 8;
                size_t base1 = (size_t)(row1 >> 6) * 32768 + (size_t)col * 64 + (row1 & 63);
                g_vt[base1]      = __float2half_rn(v10);
                g_vt[base1 + 64] = __float2half_rn(v11);
            }
        }
    }
}

// ---------------------------------------------------------------------------
// Proj GEMM: out = g_xh(fp16) @ Wp^T + bp. Single-pass fp16, all-cp.async.
// ---------------------------------------------------------------------------
#define SMEM_P  SMEM_G

__global__ __launch_bounds__(512, 1)
void gemm_proj(const float* __restrict__ bias, float* __restrict__ out) {
    extern __shared__ __half sm[];
    const uint32_t sb = (uint32_t)__cvta_generic_to_shared(sm);
    const __half* Wh = g_wblob + (size_t)3 * 262144;

    const int tid  = threadIdx.x;
    const int lane = tid & 31;
    const int wid  = tid >> 5;
    const int wm   = (wid >> 2) * 32;
    const int wn   = (wid & 3) * 64;
    const int n0   = blockIdx.x * 256;
    const int m0   = blockIdx.y * 128;

    const int arow  = tid >> 2;
    const int acolf = (tid & 3) * 8;
    const int brow  = tid >> 1;
    const int bcolf = (tid & 1) * 16;

    const int a_lrow = (lane & 15);
    const int a_lcol = (lane >> 4) * 8;
    const int b_lrow = ((lane >> 4) << 3) + (lane & 7);
    const int b_lcol = ((lane >> 3) & 1) * 8;

    float acc[2][8][4];
    #pragma unroll
    for (int i = 0; i < 2; i++)
        #pragma unroll
        for (int j = 0; j < 8; j++)
            #pragma unroll
            for (int r = 0; r < 4; r++) acc[i][j][r] = 0.f;

    auto stage = [&](int c, int st) {
        uint32_t dA = sb + (uint32_t)(st * STAGE_E + OFF_A + arow * SAK + acolf) * 2;
        cp16(dA, g_xh + (size_t)(m0 + arow) * DIMC + c * KC + acolf);
        uint32_t dB = sb + (uint32_t)(st * STAGE_E + OFF_B + brow * SAK + bcolf) * 2;
        const __half* srcB = Wh + (size_t)(n0 + brow) * DIMC + c * KC + bcolf;
        cp16(dB,      srcB);
        cp16(dB + 16, srcB + 8);
    };
    auto compute = [&](int st) {
        const uint32_t abase = sb + (uint32_t)(st * STAGE_E) * 2;
        #pragma unroll
        for (int ks = 0; ks < 2; ks++) {
            const int kc0 = ks * 16;
            uint32_t bf[8][2];
            uint32_t ah[2][4];
            #pragma unroll
            for (int i = 0; i < 2; i++) {
                ldsm_x4(ah[i], abase + (uint32_t)(OFF_A +
                    (wm + i * 16 + a_lrow) * SAK + kc0 + a_lcol) * 2);
            }
            #pragma unroll
            for (int gg = 0; gg < 4; gg++) {
                uint32_t r[4];
                ldsm_x4(r, abase + (uint32_t)(OFF_B +
                    (wn + gg * 16 + b_lrow) * SAK + kc0 + b_lcol) * 2);
                bf[2 * gg][0] = r[0]; bf[2 * gg][1] = r[1];
                bf[2 * gg + 1][0] = r[2]; bf[2 * gg + 1][1] = r[3];
            }
            #pragma unroll
            for (int i = 0; i < 2; i++)
                #pragma unroll
                for (int j = 0; j < 8; j++)
                    mma16816(acc[i][j], ah[i], bf[j]);
        }
    };

    stage(0, 0);
    asm volatile("cp.async.commit_group;" ::: "memory");

    for (int c = 0; c < 16; c++) {
        const int st  = c % 3;
        const int stn = (c + 1) % 3;
        if (c < 15) {
            stage(c + 1, stn);
            asm volatile("cp.async.commit_group;" ::: "memory");
            asm volatile("cp.async.wait_group 1;" ::: "memory");
        } else {
            asm volatile("cp.async.wait_group 0;" ::: "memory");
        }
        __syncthreads();
        compute(st);
    }

    #pragma unroll
    for (int j = 0; j < 8; j++) {
        int col = n0 + wn + j * 8 + (lane & 3) * 2;
        float b0 = __ldg(bias + col), b1 = __ldg(bias + col + 1);
        #pragma unroll
        for (int i = 0; i < 2; i++) {
            int row = m0 + wm + i * 16 + (lane >> 2);
            *(float2*)(out + (size_t)row * DIMC + col) =
                make_float2(acc[i][j][0] + b0, acc[i][j][1] + b1);
            *(float2*)(out + (size_t)(row + 8) * DIMC + col) =
                make_float2(acc[i][j][2] + b0, acc[i][j][3] + b1);
        }
    }
}

// ---------------------------------------------------------------------------
// Attention per (b,h): register-resident softmax + direct P fragments.
// S D-fragments == P A-fragments; no S smem, no P ldsm, single barrier.
// ---------------------------------------------------------------------------
#define SK2   72
#define TQH   0
#define TQL   4608
#define TKH   9216
#define TVT   13824
#define OFF_M 36864                 // bytes: mask ints after 4 tiles
#define SMEM_A (36864 + 256)

__global__ __launch_bounds__(128, 4)
void attn(const int* __restrict__ mask) {
    extern __shared__ __half sha[];
    int* smask = (int*)((char*)sha + OFF_M);
    const uint32_t sb = (uint32_t)__cvta_generic_to_shared(sha);

    const int blk  = blockIdx.x;
    const int h    = blk & (HEADS - 1);
    const int b    = blk >> 3;
    const int tid  = threadIdx.x;
    const int lane = tid & 31;
    const int wid  = tid >> 5;
    const int wm   = wid * 16;

    if (tid < NTOK) smask[tid] = mask[b * NTOK + tid];

    {
        const __half* srcq = g_qh + (size_t)(b * 64) * DIMC + h * HD;
        const __half* srcl = g_ql + (size_t)(b * 64) * DIMC + h * HD;
        const __half* srck = g_kh + (size_t)(b * 64) * DIMC + h * HD;
        const __half* srcv = g_vt + (size_t)(b * 8 + h) * 4096;
        #pragma unroll
        for (int u = 0; u < 4; u++) {
            int seg = tid * 4 + u;
            int row = seg >> 3, s8 = (seg & 7) * 8;
            uint32_t dof = (uint32_t)(row * SK2 + s8) * 2;
            cp16(sb + (uint32_t)(TQH * 2) + dof, srcq + (size_t)row * DIMC + s8);
            cp16(sb + (uint32_t)(TQL * 2) + dof, srcl + (size_t)row * DIMC + s8);
            cp16(sb + (uint32_t)(TKH * 2) + dof, srck + (size_t)row * DIMC + s8);
            cp16(sb + (uint32_t)(TVT * 2) + dof, srcv + row * 64 + s8);
        }
        asm volatile("cp.async.commit_group;" ::: "memory");
        asm volatile("cp.async.wait_group 0;" ::: "memory");
    }
    __syncthreads();

    const int a_lrow = (lane & 15);
    const int a_lcol = (lane >> 4) * 8;
    const int b_lrow = ((lane >> 4) << 3) + (lane & 7);
    const int b_lcol = ((lane >> 3) & 1) * 8;

    // ---- S = (Qh+Ql) Kh^T, kept in registers ----
    float acc[8][4];
    #pragma unroll
    for (int j = 0; j < 8; j++)
        #pragma unroll
        for (int r = 0; r < 4; r++) acc[j][r] = 0.f;
    #pragma unroll
    for (int ks = 0; ks < 4; ks++) {
        const int kc0 = ks * 16;
        uint32_t qh[4], ql[4], bf[8][2];
        uint32_t qaddr = sb + (uint32_t)(TQH + (wm + a_lrow) * SK2 + kc0 + a_lcol) * 2;
        ldsm_x4(qh, qaddr);
        ldsm_x4(ql, qaddr + (uint32_t)(TQL - TQH) * 2);
        #pragma unroll
        for (int gg = 0; gg < 4; gg++) {
            uint32_t r[4];
            ldsm_x4(r, sb + (uint32_t)(TKH + (gg * 16 + b_lrow) * SK2 + kc0 + b_lcol) * 2);
            bf[2 * gg][0] = r[0]; bf[2 * gg][1] = r[1];
            bf[2 * gg + 1][0] = r[2]; bf[2 * gg + 1][1] = r[3];
        }
        #pragma unroll
        for (int j = 0; j < 8; j++) mma16816(acc[j], qh, bf[j]);
        #pragma unroll
        for (int j = 0; j < 8; j++) mma16816(acc[j], ql, bf[j]);
    }

    // ---- masked softmax in registers (rows lane>>2 and +8) ----
    uint32_t ph[4][4], pl[4][4];
    {
        #pragma unroll
        for (int j = 0; j < 8; j++) {
            int c0 = j * 8 + (lane & 3) * 2;
            bool k0 = smask[c0] != 0, k1 = smask[c0 + 1] != 0;
            if (!k0) { acc[j][0] = -10000.f; acc[j][2] = -10000.f; }
            if (!k1) { acc[j][1] = -10000.f; acc[j][3] = -10000.f; }
        }
        float mlo = -1e30f, mhi = -1e30f;
        #pragma unroll
        for (int j = 0; j < 8; j++) {
            mlo = fmaxf(mlo, fmaxf(acc[j][0], acc[j][1]));
            mhi = fmaxf(mhi, fmaxf(acc[j][2], acc[j][3]));
        }
        mlo = fmaxf(mlo, __shfl_xor_sync(0xffffffffu, mlo, 1));
        mlo = fmaxf(mlo, __shfl_xor_sync(0xffffffffu, mlo, 2));
        mhi = fmaxf(mhi, __shfl_xor_sync(0xffffffffu, mhi, 1));
        mhi = fmaxf(mhi, __shfl_xor_sync(0xffffffffu, mhi, 2));
        float slo = 0.f, shi = 0.f;
        #pragma unroll
        for (int j = 0; j < 8; j++) {
            acc[j][0] = __expf(acc[j][0] - mlo); slo += acc[j][0];
            acc[j][1] = __expf(acc[j][1] - mlo); slo += acc[j][1];
            acc[j][2] = __expf(acc[j][2] - mhi); shi += acc[j][2];
            acc[j][3] = __expf(acc[j][3] - mhi); shi += acc[j][3];
        }
        slo += __shfl_xor_sync(0xffffffffu, slo, 1);
        slo += __shfl_xor_sync(0xffffffffu, slo, 2);
        shi += __shfl_xor_sync(0xffffffffu, shi, 1);
        shi += __shfl_xor_sync(0xffffffffu, shi, 2);
        float ilo = 1.0f / slo, ihi = 1.0f / shi;
        // build P fragments: a[0]=acc[2s][0,1] a[1]=acc[2s][2,3] a[2]=acc[2s+1][0,1] a[3]=acc[2s+1][2,3]
        #pragma unroll
        for (int s = 0; s < 4; s++) {
            #pragma unroll
            for (int half = 0; half < 2; half++) {      // 0: j=2s, 1: j=2s+1
                int j = 2 * s + half;
                float p0 = acc[j][0] * ilo, p1 = acc[j][1] * ilo;
                float p2 = acc[j][2] * ihi, p3 = acc[j][3] * ihi;
                __half h0 = __float2half_rn(p0), h1 = __float2half_rn(p1);
                __half h2 = __float2half_rn(p2), h3 = __float2half_rn(p3);
                ph[s][2 * half]     = pack_h(h0, h1);
                ph[s][2 * half + 1] = pack_h(h2, h3);
                pl[s][2 * half]     = pack_h(__float2half_rn(p0 - __half2float(h0)),
                                             __float2half_rn(p1 - __half2float(h1)));
                pl[s][2 * half + 1] = pack_h(__float2half_rn(p2 - __half2float(h2)),
                                             __float2half_rn(p3 - __half2float(h3)));
            }
        }
    }

    // ---- O = (Ph+Pl) V, reuse acc ----
    #pragma unroll
    for (int j = 0; j < 8; j++)
        #pragma unroll
        for (int r = 0; r < 4; r++) acc[j][r] = 0.f;
    #pragma unroll
    for (int ks = 0; ks < 4; ks++) {
        const int kc0 = ks * 16;
        uint32_t bf[8][2];
        #pragma unroll
        for (int gg = 0; gg < 4; gg++) {
            uint32_t r[4];
            ldsm_x4(r, sb + (uint32_t)(TVT + (gg * 16 + b_lrow) * SK2 + kc0 + b_lcol) * 2);
            bf[2 * gg][0] = r[0]; bf[2 * gg][1] = r[1];
            bf[2 * gg + 1][0] = r[2]; bf[2 * gg + 1][1] = r[3];
        }
        #pragma unroll
        for (int j = 0; j < 8; j++) mma16816(acc[j], ph[ks], bf[j]);
        #pragma unroll
        for (int j = 0; j < 8; j++) mma16816(acc[j], pl[ks], bf[j]);
    }
    #pragma unroll
    for (int j = 0; j < 8; j++) {
        int col = h * HD + j * 8 + (lane & 3) * 2;
        int r0  = wm + (lane >> 2);
        *(uint32_t*)(g_xh + (size_t)(b * 64 + r0) * DIMC + col) =
            pack_h(__float2half_rn(acc[j][0]), __float2half_rn(acc[j][1]));
        *(uint32_t*)(g_xh + (size_t)(b * 64 + r0 + 8) * DIMC + col) =
            pack_h(__float2half_rn(acc[j][2]), __float2half_rn(acc[j][3]));
    }
}

// ---------------------------------------------------------------------------
extern "C" void kernel_launch(void* const* d_in, const int* in_sizes, int n_in,
                              void* d_out, int out_size) {
    const float* q    = (const float*)d_in[0];
    const float* k    = (const float*)d_in[1];
    const float* v    = (const float*)d_in[2];
    const int*   mask = (const int*)  d_in[3];
    const float* Wq   = (const float*)d_in[4];
    const float* bq   = (const float*)d_in[5];
    const float* Wk   = (const float*)d_in[6];
    const float* bk   = (const float*)d_in[7];
    const float* Wv   = (const float*)d_in[8];
    const float* bv   = (const float*)d_in[9];
    const float* Wp   = (const float*)d_in[10];
    const float* bp   = (const float*)d_in[11];
    float* out = (float*)d_out;

    cudaFuncSetAttribute(gemm_qkv,  cudaFuncAttributeMaxDynamicSharedMemorySize, SMEM_G);
    cudaFuncSetAttribute(gemm_proj, cudaFuncAttributeMaxDynamicSharedMemorySize, SMEM_P);
    cudaFuncSetAttribute(attn,      cudaFuncAttributeMaxDynamicSharedMemorySize, SMEM_A);

    conv_w<<<4096, 256>>>(Wq, Wk, Wv, Wp);

    dim3 gqkv(DIMC / 256, MROWS / 128, 3);
    gemm_qkv<<<gqkv, 512, SMEM_G>>>(q, k, v, bq, bk, bv);

    attn<<<BATCH * HEADS, 128, SMEM_A>>>(mask);

    dim3 gp(DIMC / 256, MROWS / 128);
    gemm_proj<<<gp, 512, SMEM_P>>>(bp, out);
}

// round 17
// speedup vs baseline: 1.7506x; 1.1432x over previous
#include <cuda_runtime.h>
#include <cuda_fp16.h>
#include <cstdint>

#define DIMC   512
#define HEADS  8
#define HD     64
#define NTOK   64
#define BATCH  2048
#define MROWS  (BATCH * NTOK)     // 131072
#define SCALE_Q 0.125f

// ---------------- device scratch ----------------
__device__ __half g_qh[(size_t)MROWS * DIMC];   // Q (fp16, scale folded)
__device__ __half g_kh[(size_t)MROWS * DIMC];   // K (fp16)
__device__ __half g_vt[(size_t)MROWS * DIMC];   // V (fp16), transposed [b][h][d][token]
__device__ __half g_xh[(size_t)MROWS * DIMC];   // attn out (fp16)
__device__ __align__(128) __half g_wblob[(size_t)4 * 512 * 512];

// ---------------------------------------------------------------------------
// Kernel 0: weights -> fp16 blobs. Wq pre-scaled by SCALE_Q (exact pow2).
// ---------------------------------------------------------------------------
__global__ void conv_w(const float* __restrict__ Wq, const float* __restrict__ Wk,
                       const float* __restrict__ Wv, const float* __restrict__ Wp) {
    int idx = blockIdx.x * 256 + threadIdx.x;
    int g   = idx >> 18;
    int rem = idx & 262143;
    const float* W = (g == 0) ? Wq : (g == 1) ? Wk : (g == 2) ? Wv : Wp;
    float w = W[rem] * ((g == 0) ? SCALE_Q : 1.0f);
    g_wblob[(size_t)g * 262144 + rem] = __float2half_rn(w);
}

// ---------------------------------------------------------------------------
// common MMA helpers
// ---------------------------------------------------------------------------
__device__ __forceinline__ void mma16816(float* d, const uint32_t* a, const uint32_t* b) {
    asm volatile(
        "mma.sync.aligned.m16n8k16.row.col.f32.f16.f16.f32 "
        "{%0,%1,%2,%3}, {%4,%5,%6,%7}, {%8,%9}, {%0,%1,%2,%3};"
        : "+f"(d[0]), "+f"(d[1]), "+f"(d[2]), "+f"(d[3])
        : "r"(a[0]), "r"(a[1]), "r"(a[2]), "r"(a[3]), "r"(b[0]), "r"(b[1]));
}
__device__ __forceinline__ void ldsm_x4(uint32_t* r, uint32_t addr) {
    asm volatile("ldmatrix.sync.aligned.m8n8.x4.shared.b16 {%0,%1,%2,%3}, [%4];"
        : "=r"(r[0]), "=r"(r[1]), "=r"(r[2]), "=r"(r[3]) : "r"(addr));
}
__device__ __forceinline__ void cp16(uint32_t dst, const void* src) {
    asm volatile("cp.async.cg.shared.global [%0], [%1], 16;" :: "r"(dst), "l"(src));
}
__device__ __forceinline__ uint32_t pack_h(__half a, __half b) {
    return (uint32_t)__half_as_ushort(a) | ((uint32_t)__half_as_ushort(b) << 16);
}

// ---------------------------------------------------------------------------
// Fused QKV GEMM (grid.z = g): single-pass fp16.
// Epilogues: 0=Q->fp16, 1=K->fp16, 2=V->fp16 transposed via SMEM (coalesced).
// ---------------------------------------------------------------------------
#define KC      32
#define SAK     40
#define OFF_A   0
#define OFF_B   (128 * SAK)
#define STAGE_E (128 * SAK + 256 * SAK)
#define SMEM_G  (3 * STAGE_E * 2)                  // 92160 B (>= 128*264*2=67584)
#define VT_PAD  264                                // smem transpose stride (halves)

__global__ __launch_bounds__(512, 1)
void gemm_qkv(const float* __restrict__ qin, const float* __restrict__ kin,
              const float* __restrict__ vin,
              const float* __restrict__ bq, const float* __restrict__ bk,
              const float* __restrict__ bv) {
    extern __shared__ __half sm[];
    const uint32_t sb = (uint32_t)__cvta_generic_to_shared(sm);

    const int g = blockIdx.z;
    const float* A    = (g == 0) ? qin : (g == 1) ? kin : vin;
    const float* bias = (g == 0) ? bq  : (g == 1) ? bk  : bv;
    const __half* Wh  = g_wblob + (size_t)g * 262144;

    const int tid  = threadIdx.x;
    const int lane = tid & 31;
    const int wid  = tid >> 5;
    const int wm   = (wid >> 2) * 32;
    const int wn   = (wid & 3) * 64;
    const int n0   = blockIdx.x * 256;
    const int m0   = blockIdx.y * 128;

    const int arow  = tid >> 2;
    const int acolf = (tid & 3) * 8;
    const int brow  = tid >> 1;
    const int bcolf = (tid & 1) * 16;

    const int a_lrow = (lane & 15);
    const int a_lcol = (lane >> 4) * 8;
    const int b_lrow = ((lane >> 4) << 3) + (lane & 7);
    const int b_lcol = ((lane >> 3) & 1) * 8;

    float acc[2][8][4];
    #pragma unroll
    for (int i = 0; i < 2; i++)
        #pragma unroll
        for (int j = 0; j < 8; j++)
            #pragma unroll
            for (int r = 0; r < 4; r++) acc[i][j][r] = 0.f;

    float4 rA[2];

    auto stageB = [&](int c, int st) {
        uint32_t dst = sb + (uint32_t)(st * STAGE_E + OFF_B + brow * SAK + bcolf) * 2;
        const __half* src = Wh + (size_t)(n0 + brow) * DIMC + c * KC + bcolf;
        cp16(dst,      src);
        cp16(dst + 16, src + 8);
    };
    auto ldgA = [&](int c) {
        const float* src = A + (size_t)(m0 + arow) * DIMC + c * KC + acolf;
        rA[0] = __ldg((const float4*)src);
        rA[1] = __ldg((const float4*)(src + 4));
    };
    auto stsA = [&](int st) {
        __half* sA = sm + st * STAGE_E + OFF_A + arow * SAK + acolf;
        #pragma unroll
        for (int u = 0; u < 2; u++) {
            float4 f = rA[u];
            *(uint2*)(sA + u * 4) = make_uint2(
                pack_h(__float2half_rn(f.x), __float2half_rn(f.y)),
                pack_h(__float2half_rn(f.z), __float2half_rn(f.w)));
        }
    };
    auto compute = [&](int st) {
        const uint32_t abase = sb + (uint32_t)(st * STAGE_E) * 2;
        #pragma unroll
        for (int ks = 0; ks < 2; ks++) {
            const int kc0 = ks * 16;
            uint32_t bf[8][2];
            uint32_t ah[2][4];
            #pragma unroll
            for (int i = 0; i < 2; i++) {
                ldsm_x4(ah[i], abase + (uint32_t)(OFF_A +
                    (wm + i * 16 + a_lrow) * SAK + kc0 + a_lcol) * 2);
            }
            #pragma unroll
            for (int gg = 0; gg < 4; gg++) {
                uint32_t r[4];
                ldsm_x4(r, abase + (uint32_t)(OFF_B +
                    (wn + gg * 16 + b_lrow) * SAK + kc0 + b_lcol) * 2);
                bf[2 * gg][0] = r[0]; bf[2 * gg][1] = r[1];
                bf[2 * gg + 1][0] = r[2]; bf[2 * gg + 1][1] = r[3];
            }
            #pragma unroll
            for (int i = 0; i < 2; i++)
                #pragma unroll
                for (int j = 0; j < 8; j++)
                    mma16816(acc[i][j], ah[i], bf[j]);
        }
    };

    stageB(0, 0);
    asm volatile("cp.async.commit_group;" ::: "memory");
    ldgA(0);
    stsA(0);

    for (int c = 0; c < 16; c++) {
        const int st  = c % 3;
        const int stn = (c + 1) % 3;
        if (c < 15) {
            ldgA(c + 1);
            stageB(c + 1, stn);
            asm volatile("cp.async.commit_group;" ::: "memory");
            asm volatile("cp.async.wait_group 1;" ::: "memory");
        } else {
            asm volatile("cp.async.wait_group 0;" ::: "memory");
        }
        __syncthreads();
        compute(st);
        if (c < 15) stsA(stn);
    }

    if (g < 2) {
        // ---- Q / K: direct fp16 stores (coalesced enough: 4B x 4 lanes) ----
        __half* dst = (g == 0) ? g_qh : g_kh;
        float bscale = (g == 0) ? SCALE_Q : 1.0f;
        #pragma unroll
        for (int j = 0; j < 8; j++) {
            int col = n0 + wn + j * 8 + (lane & 3) * 2;
            float b0 = __ldg(bias + col) * bscale, b1 = __ldg(bias + col + 1) * bscale;
            #pragma unroll
            for (int i = 0; i < 2; i++) {
                int row = m0 + wm + i * 16 + (lane >> 2);
                *(uint32_t*)(dst + (size_t)row * DIMC + col) =
                    pack_h(__float2half_rn(acc[i][j][0] + b0),
                           __float2half_rn(acc[i][j][1] + b1));
                *(uint32_t*)(dst + (size_t)(row + 8) * DIMC + col) =
                    pack_h(__float2half_rn(acc[i][j][2] + b0),
                           __float2half_rn(acc[i][j][3] + b1));
            }
        }
    } else {
        // ---- V: transpose via SMEM, then coalesced 128B-row stores ----
        __syncthreads();           // staging buffers dead; reuse as sT[128][VT_PAD]
        #pragma unroll
        for (int j = 0; j < 8; j++) {
            int lcol = wn + j * 8 + (lane & 3) * 2;
            int gcol = n0 + lcol;
            float b0 = __ldg(bias + gcol), b1 = __ldg(bias + gcol + 1);
            #pragma unroll
            for (int i = 0; i < 2; i++) {
                int lrow = wm + i * 16 + (lane >> 2);
                *(uint32_t*)(sm + lrow * VT_PAD + lcol) =
                    pack_h(__float2half_rn(acc[i][j][0] + b0),
                           __float2half_rn(acc[i][j][1] + b1));
                *(uint32_t*)(sm + (lrow + 8) * VT_PAD + lcol) =
                    pack_h(__float2half_rn(acc[i][j][2] + b0),
                           __float2half_rn(acc[i][j][3] + b1));
            }
        }
        __syncthreads();
        // 512 output rows: (tb in 0..1) x (cc in 0..255); each row = 64 tokens = 128B
        const int tb = tid >> 8;
        const int cc = tid & 255;
        const __half* srow = sm + (tb * 64) * VT_PAD + cc;
        __half* drow = g_vt + (size_t)((m0 >> 6) + tb) * 32768 + (size_t)(n0 + cc) * 64;
        #pragma unroll
        for (int t8 = 0; t8 < 8; t8++) {
            __half tmp[8];
            #pragma unroll
            for (int t = 0; t < 8; t++)
                tmp[t] = srow[(t8 * 8 + t) * VT_PAD];
            *(uint4*)(drow + t8 * 8) = *(uint4*)tmp;
        }
    }
}

// ---------------------------------------------------------------------------
// Proj GEMM: out = g_xh(fp16) @ Wp^T + bp. Single-pass fp16, all-cp.async.
// ---------------------------------------------------------------------------
#define SMEM_P  SMEM_G

__global__ __launch_bounds__(512, 1)
void gemm_proj(const float* __restrict__ bias, float* __restrict__ out) {
    extern __shared__ __half sm[];
    const uint32_t sb = (uint32_t)__cvta_generic_to_shared(sm);
    const __half* Wh = g_wblob + (size_t)3 * 262144;

    const int tid  = threadIdx.x;
    const int lane = tid & 31;
    const int wid  = tid >> 5;
    const int wm   = (wid >> 2) * 32;
    const int wn   = (wid & 3) * 64;
    const int n0   = blockIdx.x * 256;
    const int m0   = blockIdx.y * 128;

    const int arow  = tid >> 2;
    const int acolf = (tid & 3) * 8;
    const int brow  = tid >> 1;
    const int bcolf = (tid & 1) * 16;

    const int a_lrow = (lane & 15);
    const int a_lcol = (lane >> 4) * 8;
    const int b_lrow = ((lane >> 4) << 3) + (lane & 7);
    const int b_lcol = ((lane >> 3) & 1) * 8;

    float acc[2][8][4];
    #pragma unroll
    for (int i = 0; i < 2; i++)
        #pragma unroll
        for (int j = 0; j < 8; j++)
            #pragma unroll
            for (int r = 0; r < 4; r++) acc[i][j][r] = 0.f;

    auto stage = [&](int c, int st) {
        uint32_t dA = sb + (uint32_t)(st * STAGE_E + OFF_A + arow * SAK + acolf) * 2;
        cp16(dA, g_xh + (size_t)(m0 + arow) * DIMC + c * KC + acolf);
        uint32_t dB = sb + (uint32_t)(st * STAGE_E + OFF_B + brow * SAK + bcolf) * 2;
        const __half* srcB = Wh + (size_t)(n0 + brow) * DIMC + c * KC + bcolf;
        cp16(dB,      srcB);
        cp16(dB + 16, srcB + 8);
    };
    auto compute = [&](int st) {
        const uint32_t abase = sb + (uint32_t)(st * STAGE_E) * 2;
        #pragma unroll
        for (int ks = 0; ks < 2; ks++) {
            const int kc0 = ks * 16;
            uint32_t bf[8][2];
            uint32_t ah[2][4];
            #pragma unroll
            for (int i = 0; i < 2; i++) {
                ldsm_x4(ah[i], abase + (uint32_t)(OFF_A +
                    (wm + i * 16 + a_lrow) * SAK + kc0 + a_lcol) * 2);
            }
            #pragma unroll
            for (int gg = 0; gg < 4; gg++) {
                uint32_t r[4];
                ldsm_x4(r, abase + (uint32_t)(OFF_B +
                    (wn + gg * 16 + b_lrow) * SAK + kc0 + b_lcol) * 2);
                bf[2 * gg][0] = r[0]; bf[2 * gg][1] = r[1];
                bf[2 * gg + 1][0] = r[2]; bf[2 * gg + 1][1] = r[3];
            }
            #pragma unroll
            for (int i = 0; i < 2; i++)
                #pragma unroll
                for (int j = 0; j < 8; j++)
                    mma16816(acc[i][j], ah[i], bf[j]);
        }
    };

    stage(0, 0);
    asm volatile("cp.async.commit_group;" ::: "memory");

    for (int c = 0; c < 16; c++) {
        const int st  = c % 3;
        const int stn = (c + 1) % 3;
        if (c < 15) {
            stage(c + 1, stn);
            asm volatile("cp.async.commit_group;" ::: "memory");
            asm volatile("cp.async.wait_group 1;" ::: "memory");
        } else {
            asm volatile("cp.async.wait_group 0;" ::: "memory");
        }
        __syncthreads();
        compute(st);
    }

    #pragma unroll
    for (int j = 0; j < 8; j++) {
        int col = n0 + wn + j * 8 + (lane & 3) * 2;
        float b0 = __ldg(bias + col), b1 = __ldg(bias + col + 1);
        #pragma unroll
        for (int i = 0; i < 2; i++) {
            int row = m0 + wm + i * 16 + (lane >> 2);
            *(float2*)(out + (size_t)row * DIMC + col) =
                make_float2(acc[i][j][0] + b0, acc[i][j][1] + b1);
            *(float2*)(out + (size_t)(row + 8) * DIMC + col) =
                make_float2(acc[i][j][2] + b0, acc[i][j][3] + b1);
        }
    }
}

// ---------------------------------------------------------------------------
// Attention per (b,h): 3 fp16 tiles (Q,K,Vt), register softmax, P hi/lo.
// ---------------------------------------------------------------------------
#define SK2   72
#define TQH   0
#define TKH   4608
#define TVT   9216
#define OFF_M 27648                 // bytes: mask after 3 tiles
#define SMEM_A (27648 + 256)

__global__ __launch_bounds__(128, 4)
void attn(const int* __restrict__ mask) {
    extern __shared__ __half sha[];
    int* smask = (int*)((char*)sha + OFF_M);
    const uint32_t sb = (uint32_t)__cvta_generic_to_shared(sha);

    const int blk  = blockIdx.x;
    const int h    = blk & (HEADS - 1);
    const int b    = blk >> 3;
    const int tid  = threadIdx.x;
    const int lane = tid & 31;
    const int wid  = tid >> 5;
    const int wm   = wid * 16;

    if (tid < NTOK) smask[tid] = mask[b * NTOK + tid];

    {
        const __half* srcq = g_qh + (size_t)(b * 64) * DIMC + h * HD;
        const __half* srck = g_kh + (size_t)(b * 64) * DIMC + h * HD;
        const __half* srcv = g_vt + (size_t)(b * 8 + h) * 4096;
        #pragma unroll
        for (int u = 0; u < 4; u++) {
            int seg = tid * 4 + u;
            int row = seg >> 3, s8 = (seg & 7) * 8;
            uint32_t dof = (uint32_t)(row * SK2 + s8) * 2;
            cp16(sb + (uint32_t)(TQH * 2) + dof, srcq + (size_t)row * DIMC + s8);
            cp16(sb + (uint32_t)(TKH * 2) + dof, srck + (size_t)row * DIMC + s8);
            cp16(sb + (uint32_t)(TVT * 2) + dof, srcv + row * 64 + s8);
        }
        asm volatile("cp.async.commit_group;" ::: "memory");
        asm volatile("cp.async.wait_group 0;" ::: "memory");
    }
    __syncthreads();

    const int a_lrow = (lane & 15);
    const int a_lcol = (lane >> 4) * 8;
    const int b_lrow = ((lane >> 4) << 3) + (lane & 7);
    const int b_lcol = ((lane >> 3) & 1) * 8;

    // ---- S = Q Kh^T (single-pass fp16 Q), kept in registers ----
    float acc[8][4];
    #pragma unroll
    for (int j = 0; j < 8; j++)
        #pragma unroll
        for (int r = 0; r < 4; r++) acc[j][r] = 0.f;
    #pragma unroll
    for (int ks = 0; ks < 4; ks++) {
        const int kc0 = ks * 16;
        uint32_t qh[4], bf[8][2];
        ldsm_x4(qh, sb + (uint32_t)(TQH + (wm + a_lrow) * SK2 + kc0 + a_lcol) * 2);
        #pragma unroll
        for (int gg = 0; gg < 4; gg++) {
            uint32_t r[4];
            ldsm_x4(r, sb + (uint32_t)(TKH + (gg * 16 + b_lrow) * SK2 + kc0 + b_lcol) * 2);
            bf[2 * gg][0] = r[0]; bf[2 * gg][1] = r[1];
            bf[2 * gg + 1][0] = r[2]; bf[2 * gg + 1][1] = r[3];
        }
        #pragma unroll
        for (int j = 0; j < 8; j++) mma16816(acc[j], qh, bf[j]);
    }

    // ---- masked softmax in registers ----
    uint32_t ph[4][4], pl[4][4];
    {
        #pragma unroll
        for (int j = 0; j < 8; j++) {
            int c0 = j * 8 + (lane & 3) * 2;
            bool k0 = smask[c0] != 0, k1 = smask[c0 + 1] != 0;
            if (!k0) { acc[j][0] = -10000.f; acc[j][2] = -10000.f; }
            if (!k1) { acc[j][1] = -10000.f; acc[j][3] = -10000.f; }
        }
        float mlo = -1e30f, mhi = -1e30f;
        #pragma unroll
        for (int j = 0; j < 8; j++) {
            mlo = fmaxf(mlo, fmaxf(acc[j][0], acc[j][1]));
            mhi = fmaxf(mhi, fmaxf(acc[j][2], acc[j][3]));
        }
        mlo = fmaxf(mlo, __shfl_xor_sync(0xffffffffu, mlo, 1));
        mlo = fmaxf(mlo, __shfl_xor_sync(0xffffffffu, mlo, 2));
        mhi = fmaxf(mhi, __shfl_xor_sync(0xffffffffu, mhi, 1));
        mhi = fmaxf(mhi, __shfl_xor_sync(0xffffffffu, mhi, 2));
        float slo = 0.f, shi = 0.f;
        #pragma unroll
        for (int j = 0; j < 8; j++) {
            acc[j][0] = __expf(acc[j][0] - mlo); slo += acc[j][0];
            acc[j][1] = __expf(acc[j][1] - mlo); slo += acc[j][1];
            acc[j][2] = __expf(acc[j][2] - mhi); shi += acc[j][2];
            acc[j][3] = __expf(acc[j][3] - mhi); shi += acc[j][3];
        }
        slo += __shfl_xor_sync(0xffffffffu, slo, 1);
        slo += __shfl_xor_sync(0xffffffffu, slo, 2);
        shi += __shfl_xor_sync(0xffffffffu, shi, 1);
        shi += __shfl_xor_sync(0xffffffffu, shi, 2);
        float ilo = 1.0f / slo, ihi = 1.0f / shi;
        #pragma unroll
        for (int s = 0; s < 4; s++) {
            #pragma unroll
            for (int half = 0; half < 2; half++) {
                int j = 2 * s + half;
                float p0 = acc[j][0] * ilo, p1 = acc[j][1] * ilo;
                float p2 = acc[j][2] * ihi, p3 = acc[j][3] * ihi;
                __half h0 = __float2half_rn(p0), h1 = __float2half_rn(p1);
                __half h2 = __float2half_rn(p2), h3 = __float2half_rn(p3);
                ph[s][2 * half]     = pack_h(h0, h1);
                ph[s][2 * half + 1] = pack_h(h2, h3);
                pl[s][2 * half]     = pack_h(__float2half_rn(p0 - __half2float(h0)),
                                             __float2half_rn(p1 - __half2float(h1)));
                pl[s][2 * half + 1] = pack_h(__float2half_rn(p2 - __half2float(h2)),
                                             __float2half_rn(p3 - __half2float(h3)));
            }
        }
    }

    // ---- O = (Ph+Pl) V ----
    #pragma unroll
    for (int j = 0; j < 8; j++)
        #pragma unroll
        for (int r = 0; r < 4; r++) acc[j][r] = 0.f;
    #pragma unroll
    for (int ks = 0; ks < 4; ks++) {
        const int kc0 = ks * 16;
        uint32_t bf[8][2];
        #pragma unroll
        for (int gg = 0; gg < 4; gg++) {
            uint32_t r[4];
            ldsm_x4(r, sb + (uint32_t)(TVT + (gg * 16 + b_lrow) * SK2 + kc0 + b_lcol) * 2);
            bf[2 * gg][0] = r[0]; bf[2 * gg][1] = r[1];
            bf[2 * gg + 1][0] = r[2]; bf[2 * gg + 1][1] = r[3];
        }
        #pragma unroll
        for (int j = 0; j < 8; j++) mma16816(acc[j], ph[ks], bf[j]);
        #pragma unroll
        for (int j = 0; j < 8; j++) mma16816(acc[j], pl[ks], bf[j]);
    }
    #pragma unroll
    for (int j = 0; j < 8; j++) {
        int col = h * HD + j * 8 + (lane & 3) * 2;
        int r0  = wm + (lane >> 2);
        *(uint32_t*)(g_xh + (size_t)(b * 64 + r0) * DIMC + col) =
            pack_h(__float2half_rn(acc[j][0]), __float2half_rn(acc[j][1]));
        *(uint32_t*)(g_xh + (size_t)(b * 64 + r0 + 8) * DIMC + col) =
            pack_h(__float2half_rn(acc[j][2]), __float2half_rn(acc[j][3]));
    }
}

// ---------------------------------------------------------------------------
extern "C" void kernel_launch(void* const* d_in, const int* in_sizes, int n_in,
                              void* d_out, int out_size) {
    const float* q    = (const float*)d_in[0];
    const float* k    = (const float*)d_in[1];
    const float* v    = (const float*)d_in[2];
    const int*   mask = (const int*)  d_in[3];
    const float* Wq   = (const float*)d_in[4];
    const float* bq   = (const float*)d_in[5];
    const float* Wk   = (const float*)d_in[6];
    const float* bk   = (const float*)d_in[7];
    const float* Wv   = (const float*)d_in[8];
    const float* bv   = (const float*)d_in[9];
    const float* Wp   = (const float*)d_in[10];
    const float* bp   = (const float*)d_in[11];
    float* out = (float*)d_out;

    cudaFuncSetAttribute(gemm_qkv,  cudaFuncAttributeMaxDynamicSharedMemorySize, SMEM_G);
    cudaFuncSetAttribute(gemm_proj, cudaFuncAttributeMaxDynamicSharedMemorySize, SMEM_P);
    cudaFuncSetAttribute(attn,      cudaFuncAttributeMaxDynamicSharedMemorySize, SMEM_A);

    conv_w<<<4096, 256>>>(Wq, Wk, Wv, Wp);

    dim3 gqkv(DIMC / 256, MROWS / 128, 3);
    gemm_qkv<<<gqkv, 512, SMEM_G>>>(q, k, v, bq, bk, bv);

    attn<<<BATCH * HEADS, 128, SMEM_A>>>(mask);

    dim3 gp(DIMC / 256, MROWS / 128);
    gemm_proj<<<gp, 512, SMEM_P>>>(bp, out);
}